// round 2
// baseline (speedup 1.0000x reference)
#include <cuda_runtime.h>
#include <cuda_bf16.h>
#include <math.h>

// ---------------- problem constants ----------------
#define L_TXT 256
#define L_IMG 1024
#define L_TMP 1024
#define L_ALL 2304          // txt + img + tmp
#define D_MODEL 1024
#define NH 16
#define HD 64
#define D_MLP 4096
#define EPS 1e-6f
#define ATTN_SCALE 0.125f   // 1/sqrt(64)

// ---------------- scratch (static device memory; no allocation) ----------------
__device__ float g_sv[D_MODEL];
__device__ float g_mod[3 * 6144];
__device__ float g_xm[L_ALL * D_MODEL];        // LN1-modulated, concat order [txt|img|tmp]
__device__ float g_qkv[L_ALL * 3 * D_MODEL];   // QKV gemm out, same row order
__device__ float g_Q[NH * L_ALL * HD];
__device__ float g_K[NH * L_ALL * HD];
__device__ float g_V[NH * L_ALL * HD];
__device__ float g_attn[L_ALL * D_MODEL];      // [l][h*64+d], concat order
__device__ float g_x1[L_ALL * D_MODEL];        // post-proj residual, concat order
__device__ float g_ym[1024 * D_MODEL];         // LN2-modulated (per-stream reuse)
__device__ float g_h[1024 * D_MLP];            // MLP hidden (per-stream reuse)

// ---------------- helpers ----------------
__device__ __forceinline__ float gelu_tanh(float x) {
    const float c = 0.7978845608028654f; // sqrt(2/pi)
    float x3 = x * x * x;
    return 0.5f * x * (1.f + tanhf(c * (x + 0.044715f * x3)));
}

// ---------------- silu(vec) ----------------
__global__ void silu_kernel(const float* __restrict__ v, float* __restrict__ sv) {
    int t = threadIdx.x;
    float x = v[t];
    sv[t] = x / (1.f + expf(-x));
}

// ---------------- mod = sv @ mod_w + mod_b  (3 x 6144 outputs) ----------------
__global__ void mod_kernel(const float* __restrict__ sv, const float* __restrict__ mod_w,
                           const float* __restrict__ mod_b, float* __restrict__ mod) {
    __shared__ float s_sv[D_MODEL];
    for (int i = threadIdx.x; i < D_MODEL; i += 256) s_sv[i] = sv[i];
    __syncthreads();
    int o = blockIdx.x * 256 + threadIdx.x;       // 0 .. 3*6144-1
    int i = o / 6144;
    int j = o - i * 6144;
    const float* w = mod_w + (size_t)i * D_MODEL * 6144 + j;
    float acc = 0.f;
    #pragma unroll 8
    for (int d = 0; d < D_MODEL; ++d) acc = fmaf(s_sv[d], w[(size_t)d * 6144], acc);
    mod[o] = acc + mod_b[o];
}

// ---------------- LN + modulate: out = (1+sc)*ln(x) + sh ----------------
__global__ void lnmod_kernel(const float* __restrict__ x, float* __restrict__ out,
                             const float* __restrict__ sh, const float* __restrict__ sc) {
    int r = blockIdx.x;
    const float* xr = x + (size_t)r * D_MODEL;
    int t = threadIdx.x; // 256
    float v[4]; float sum = 0.f, sq = 0.f;
    #pragma unroll
    for (int i = 0; i < 4; i++) { float f = xr[t + i * 256]; v[i] = f; sum += f; sq += f * f; }
    #pragma unroll
    for (int o = 16; o; o >>= 1) {
        sum += __shfl_xor_sync(0xffffffffu, sum, o);
        sq  += __shfl_xor_sync(0xffffffffu, sq, o);
    }
    __shared__ float ssum[8], ssq[8];
    int w = t >> 5, lane = t & 31;
    if (lane == 0) { ssum[w] = sum; ssq[w] = sq; }
    __syncthreads();
    if (t == 0) {
        float S = 0.f, Q = 0.f;
        #pragma unroll
        for (int i = 0; i < 8; i++) { S += ssum[i]; Q += ssq[i]; }
        float mean = S * (1.f / D_MODEL);
        float var  = Q * (1.f / D_MODEL) - mean * mean;
        ssum[0] = mean; ssq[0] = rsqrtf(var + EPS);
    }
    __syncthreads();
    float mean = ssum[0], inv = ssq[0];
    float* orow = out + (size_t)r * D_MODEL;
    #pragma unroll
    for (int i = 0; i < 4; i++) {
        int d = t + i * 256;
        orow[d] = (1.f + sc[d]) * ((v[i] - mean) * inv) + sh[d];
    }
}

// ---------------- generic tiled SGEMM: C = A(MxK) @ B(KxN), epilogues ----------------
// epi 0: C = acc
// epi 1: C = gelu(acc + bias[col])
// epi 2: C = res[row][col] + gate[col] * (acc + bias[col])
#define BM 128
#define BN 128
#define BK 8
__global__ void sgemm_kernel(const float* __restrict__ A, const float* __restrict__ B,
                             float* __restrict__ C, int M, int N, int K,
                             const float* __restrict__ bias,
                             const float* __restrict__ gate,
                             const float* __restrict__ res,
                             int epi) {
    __shared__ float As[BK][BM + 4];   // pad 132 (keeps 16B alignment: 132*4=528=33*16)
    __shared__ float Bs[BK][BN];
    int tid = threadIdx.x;                 // 256
    int brow = blockIdx.y, bcol = blockIdx.x;

    int a_row = tid >> 1;                  // 0..127
    int a_q   = (tid & 1) * 4;             // 0 or 4
    int b_row = tid >> 5;                  // 0..7
    int b_col = (tid & 31) * 4;            // 0..124
    int tm = (tid >> 4) * 8;               // 0..120
    int tn = (tid & 15) * 8;               // 0..120

    const float* Aptr = A + ((size_t)(brow * BM + a_row)) * K + a_q;
    const float* Bptr = B + (size_t)b_row * N + bcol * BN + b_col;

    float acc[8][8];
    #pragma unroll
    for (int i = 0; i < 8; i++)
        #pragma unroll
        for (int j = 0; j < 8; j++) acc[i][j] = 0.f;

    for (int k0 = 0; k0 < K; k0 += BK) {
        float4 av = *(const float4*)(Aptr + k0);
        As[a_q + 0][a_row] = av.x;
        As[a_q + 1][a_row] = av.y;
        As[a_q + 2][a_row] = av.z;
        As[a_q + 3][a_row] = av.w;
        *(float4*)&Bs[b_row][b_col] = *(const float4*)(Bptr + (size_t)k0 * N);
        __syncthreads();
        #pragma unroll
        for (int kk = 0; kk < BK; ++kk) {
            float a[8], b[8];
            float4 a0 = *(const float4*)&As[kk][tm];
            float4 a1 = *(const float4*)&As[kk][tm + 4];
            a[0]=a0.x; a[1]=a0.y; a[2]=a0.z; a[3]=a0.w;
            a[4]=a1.x; a[5]=a1.y; a[6]=a1.z; a[7]=a1.w;
            float4 b0 = *(const float4*)&Bs[kk][tn];
            float4 b1 = *(const float4*)&Bs[kk][tn + 4];
            b[0]=b0.x; b[1]=b0.y; b[2]=b0.z; b[3]=b0.w;
            b[4]=b1.x; b[5]=b1.y; b[6]=b1.z; b[7]=b1.w;
            #pragma unroll
            for (int i = 0; i < 8; i++)
                #pragma unroll
                for (int j = 0; j < 8; j++)
                    acc[i][j] = fmaf(a[i], b[j], acc[i][j]);
        }
        __syncthreads();
    }

    #pragma unroll
    for (int i = 0; i < 8; i++) {
        size_t row = (size_t)(brow * BM + tm + i);
        #pragma unroll
        for (int j = 0; j < 8; j++) {
            int col = bcol * BN + tn + j;
            float v = acc[i][j];
            if (epi == 1)      v = gelu_tanh(v + bias[col]);
            else if (epi == 2) v = res[row * N + col] + gate[col] * (v + bias[col]);
            C[row * N + col] = v;
        }
    }
}

// ---------------- QKV post: RMS + scale + RoPE + scatter to head-major ----------------
// Reference quirks replicated:
//   * V for the temporal rows (l >= 1280) is the RMS'd+scaled q BEFORE RoPE
//   * stream map (concat order): l<256 -> txt(stream 2), l<1280 -> img(0), else tmp(1)
__global__ void qkvpost_kernel(const float* __restrict__ Y, const float* __restrict__ pe,
                               const float* __restrict__ q_scale, const float* __restrict__ k_scale,
                               float* __restrict__ Q, float* __restrict__ K, float* __restrict__ V) {
    int gw = blockIdx.x * 8 + (threadIdx.x >> 5);   // warp id: 0 .. 2304*16-1
    int lane = threadIdx.x & 31;
    int l = gw >> 4;
    int h = gw & 15;
    int i = (l < L_TXT) ? 2 : (l < (L_TXT + L_IMG) ? 0 : 1);
    bool is_tmp = (l >= L_TXT + L_IMG);

    const float* row = Y + (size_t)l * 3072 + h * HD;
    float q0 = row[2 * lane],        q1 = row[2 * lane + 1];
    float k0 = row[1024 + 2 * lane], k1 = row[1024 + 2 * lane + 1];
    float v0 = row[2048 + 2 * lane], v1 = row[2048 + 2 * lane + 1];

    float qs = q0 * q0 + q1 * q1;
    float ks = k0 * k0 + k1 * k1;
    #pragma unroll
    for (int o = 16; o; o >>= 1) {
        qs += __shfl_xor_sync(0xffffffffu, qs, o);
        ks += __shfl_xor_sync(0xffffffffu, ks, o);
    }
    float qinv = rsqrtf(qs * (1.f / HD) + EPS);
    float kinv = rsqrtf(ks * (1.f / HD) + EPS);

    float qn0 = q0 * qinv * q_scale[i * HD + 2 * lane];
    float qn1 = q1 * qinv * q_scale[i * HD + 2 * lane + 1];
    float kn0 = k0 * kinv * k_scale[i * HD + 2 * lane];
    float kn1 = k1 * kinv * k_scale[i * HD + 2 * lane + 1];

    // pe[l][dd=lane][j][c], index = ((l*32+dd)*2 + j)*2 + c
    const float* p = pe + ((size_t)l * 32 + lane) * 4;
    float p00 = p[0], p01 = p[1], p10 = p[2], p11 = p[3];

    size_t base = ((size_t)h * L_ALL + l) * HD + 2 * lane;
    Q[base]     = p00 * qn0 + p01 * qn1;
    Q[base + 1] = p10 * qn0 + p11 * qn1;
    K[base]     = p00 * kn0 + p01 * kn1;
    K[base + 1] = p10 * kn0 + p11 * kn1;
    if (is_tmp) { V[base] = qn0; V[base + 1] = qn1; }
    else        { V[base] = v0;  V[base + 1] = v1;  }
}

// ---------------- flash attention (fp32): 64 q-rows/block, 32-key tiles ----------------
#define AQ 64
#define AK 32
__global__ void attn_kernel(const float* __restrict__ Q, const float* __restrict__ K,
                            const float* __restrict__ V, float* __restrict__ Aout) {
    __shared__ float Qs[AQ][65];
    __shared__ float Ks[AK][65];
    __shared__ float Vs[AK][65];
    __shared__ float Ps[AQ][33];

    int h  = blockIdx.y;
    int q0 = blockIdx.x * AQ;
    int tid = threadIdx.x;           // 256
    int qr = tid >> 2;               // 0..63
    int part = tid & 3;              // 0..3

    const float* Qh = Q + (size_t)h * L_ALL * HD;
    const float* Kh = K + (size_t)h * L_ALL * HD;
    const float* Vh = V + (size_t)h * L_ALL * HD;

    for (int idx = tid; idx < AQ * HD; idx += 256) {
        int r = idx >> 6, d = idx & 63;
        Qs[r][d] = Qh[(size_t)(q0 + r) * HD + d];
    }
    float m = -INFINITY, lsum = 0.f;
    float o[16];
    #pragma unroll
    for (int i = 0; i < 16; i++) o[i] = 0.f;
    __syncthreads();

    for (int k0 = 0; k0 < L_ALL; k0 += AK) {
        for (int idx = tid; idx < AK * HD; idx += 256) {
            int r = idx >> 6, d = idx & 63;
            Ks[r][d] = Kh[(size_t)(k0 + r) * HD + d];
            Vs[r][d] = Vh[(size_t)(k0 + r) * HD + d];
        }
        __syncthreads();

        float s[8];
        #pragma unroll
        for (int j = 0; j < 8; j++) {
            int kk = part * 8 + j;
            float acc = 0.f;
            #pragma unroll
            for (int d = 0; d < HD; d++) acc = fmaf(Qs[qr][d], Ks[kk][d], acc);
            s[j] = acc * ATTN_SCALE;
        }
        float tmax = s[0];
        #pragma unroll
        for (int j = 1; j < 8; j++) tmax = fmaxf(tmax, s[j]);
        tmax = fmaxf(tmax, __shfl_xor_sync(0xffffffffu, tmax, 1));
        tmax = fmaxf(tmax, __shfl_xor_sync(0xffffffffu, tmax, 2));
        float mnew = fmaxf(m, tmax);
        float alpha = __expf(m - mnew);
        float tsum = 0.f;
        #pragma unroll
        for (int j = 0; j < 8; j++) {
            float pv = __expf(s[j] - mnew);
            Ps[qr][part * 8 + j] = pv;
            tsum += pv;
        }
        tsum += __shfl_xor_sync(0xffffffffu, tsum, 1);
        tsum += __shfl_xor_sync(0xffffffffu, tsum, 2);
        lsum = lsum * alpha + tsum;
        m = mnew;
        #pragma unroll
        for (int i = 0; i < 16; i++) o[i] *= alpha;
        __syncthreads();
        #pragma unroll
        for (int kk = 0; kk < AK; kk++) {
            float pv = Ps[qr][kk];
            #pragma unroll
            for (int i = 0; i < 16; i++)
                o[i] = fmaf(pv, Vs[kk][part * 16 + i], o[i]);
        }
        __syncthreads();
    }

    float inv = 1.f / lsum;
    int l = q0 + qr;
    float* out = Aout + (size_t)l * D_MODEL + h * HD + part * 16;
    #pragma unroll
    for (int i = 0; i < 16; i++) out[i] = o[i] * inv;
}

// ---------------- host launch ----------------
static void launch_gemm(const float* A, const float* B, float* C, int M, int N, int K,
                        const float* bias, const float* gate, const float* res, int epi) {
    dim3 grid(N / BN, M / BM);
    sgemm_kernel<<<grid, 256>>>(A, B, C, M, N, K, bias, gate, res, epi);
}

extern "C" void kernel_launch(void* const* d_in, const int* in_sizes, int n_in,
                              void* d_out, int out_size) {
    const float* img      = (const float*)d_in[0];
    const float* temporal = (const float*)d_in[1];
    const float* txt      = (const float*)d_in[2];
    const float* vec      = (const float*)d_in[3];
    const float* pe       = (const float*)d_in[4];
    const float* mod_w    = (const float*)d_in[5];
    const float* mod_b    = (const float*)d_in[6];
    const float* qkv_w    = (const float*)d_in[7];
    const float* q_scale  = (const float*)d_in[8];
    const float* k_scale  = (const float*)d_in[9];
    const float* proj_w   = (const float*)d_in[10];
    const float* proj_b   = (const float*)d_in[11];
    const float* mlp_w1   = (const float*)d_in[12];
    const float* mlp_b1   = (const float*)d_in[13];
    const float* mlp_w2   = (const float*)d_in[14];
    const float* mlp_b2   = (const float*)d_in[15];
    float* out = (float*)d_out;
    float* out_img = out;
    float* out_tmp = out + (size_t)L_IMG * D_MODEL;
    float* out_txt = out + (size_t)(L_IMG + L_TMP) * D_MODEL;

    // Cache scratch addresses on first (non-captured, correctness) call so that
    // the captured call contains kernel launches ONLY.
    static float *sv = 0, *mod = 0, *xm = 0, *qkv = 0, *Qb = 0, *Kb = 0, *Vb = 0,
                 *attn = 0, *x1 = 0, *ym = 0, *hbuf = 0;
    if (!sv) {
        cudaGetSymbolAddress((void**)&sv,   g_sv);
        cudaGetSymbolAddress((void**)&mod,  g_mod);
        cudaGetSymbolAddress((void**)&xm,   g_xm);
        cudaGetSymbolAddress((void**)&qkv,  g_qkv);
        cudaGetSymbolAddress((void**)&Qb,   g_Q);
        cudaGetSymbolAddress((void**)&Kb,   g_K);
        cudaGetSymbolAddress((void**)&Vb,   g_V);
        cudaGetSymbolAddress((void**)&attn, g_attn);
        cudaGetSymbolAddress((void**)&x1,   g_x1);
        cudaGetSymbolAddress((void**)&ym,   g_ym);
        cudaGetSymbolAddress((void**)&hbuf, g_h);
    }

    // concat-order row offsets (rows of 1024 floats)
    const size_t off_txt = 0;
    const size_t off_img = (size_t)L_TXT * D_MODEL;
    const size_t off_tmp = (size_t)(L_TXT + L_IMG) * D_MODEL;

    // 1. sv = silu(vec)
    silu_kernel<<<1, 1024>>>(vec, sv);
    // 2. mod = sv @ mod_w + mod_b
    mod_kernel<<<(3 * 6144) / 256, 256>>>(sv, mod_w, mod_b, mod);

    // 3. LN1 + modulate (per stream; concat order txt|img|tmp)
    lnmod_kernel<<<L_TXT, 256>>>(txt,      xm + off_txt, mod + 2 * 6144,        mod + 2 * 6144 + 1024);
    lnmod_kernel<<<L_IMG, 256>>>(img,      xm + off_img, mod + 0,               mod + 1024);
    lnmod_kernel<<<L_TMP, 256>>>(temporal, xm + off_tmp, mod + 1 * 6144,        mod + 1 * 6144 + 1024);

    // 4. QKV GEMMs (per-stream weights)
    launch_gemm(xm + off_txt, qkv_w + (size_t)2 * D_MODEL * 3072, qkv + (size_t)0 * 3072,    L_TXT, 3072, D_MODEL, 0, 0, 0, 0);
    launch_gemm(xm + off_img, qkv_w + (size_t)0 * D_MODEL * 3072, qkv + (size_t)L_TXT * 3072, L_IMG, 3072, D_MODEL, 0, 0, 0, 0);
    launch_gemm(xm + off_tmp, qkv_w + (size_t)1 * D_MODEL * 3072, qkv + (size_t)(L_TXT + L_IMG) * 3072, L_TMP, 3072, D_MODEL, 0, 0, 0, 0);

    // 5. RMS + scale + RoPE + scatter (and the v<-tmp_q quirk)
    qkvpost_kernel<<<(L_ALL * NH) / 8, 256>>>(qkv, pe, q_scale, k_scale, Qb, Kb, Vb);

    // 6. attention
    attn_kernel<<<dim3(L_ALL / AQ, NH), 256>>>(Qb, Kb, Vb, attn);

    // 7. proj + gate + residual -> x1 (per stream)
    launch_gemm(attn + off_txt, proj_w + (size_t)2 * D_MODEL * D_MODEL, x1 + off_txt, L_TXT, D_MODEL, D_MODEL,
                proj_b + 2 * 1024, mod + 2 * 6144 + 2048, txt, 2);
    launch_gemm(attn + off_img, proj_w + (size_t)0,                     x1 + off_img, L_IMG, D_MODEL, D_MODEL,
                proj_b + 0,        mod + 0 * 6144 + 2048, img, 2);
    launch_gemm(attn + off_tmp, proj_w + (size_t)1 * D_MODEL * D_MODEL, x1 + off_tmp, L_TMP, D_MODEL, D_MODEL,
                proj_b + 1 * 1024, mod + 1 * 6144 + 2048, temporal, 2);

    // 8. img MLP (must finish before temporal's LN-of-final-img)
    lnmod_kernel<<<L_IMG, 256>>>(x1 + off_img, ym, mod + 0 * 6144 + 3072, mod + 0 * 6144 + 4096);
    launch_gemm(ym, mlp_w1 + (size_t)0, hbuf, L_IMG, D_MLP, D_MODEL, mlp_b1 + 0, 0, 0, 1);
    launch_gemm(hbuf, mlp_w2 + (size_t)0, out_img, L_IMG, D_MODEL, D_MLP,
                mlp_b2 + 0, mod + 0 * 6144 + 5120, x1 + off_img, 2);

    // 9. temporal MLP: LN of FINAL img (reference quirk), residual = x1_tmp
    lnmod_kernel<<<L_TMP, 256>>>(out_img, ym, mod + 1 * 6144 + 3072, mod + 1 * 6144 + 4096);
    launch_gemm(ym, mlp_w1 + (size_t)1 * D_MODEL * D_MLP, hbuf, L_TMP, D_MLP, D_MODEL, mlp_b1 + D_MLP, 0, 0, 1);
    launch_gemm(hbuf, mlp_w2 + (size_t)1 * D_MLP * D_MODEL, out_tmp, L_TMP, D_MODEL, D_MLP,
                mlp_b2 + 1024, mod + 1 * 6144 + 5120, x1 + off_tmp, 2);

    // 10. txt MLP
    lnmod_kernel<<<L_TXT, 256>>>(x1 + off_txt, ym, mod + 2 * 6144 + 3072, mod + 2 * 6144 + 4096);
    launch_gemm(ym, mlp_w1 + (size_t)2 * D_MODEL * D_MLP, hbuf, L_TXT, D_MLP, D_MODEL, mlp_b1 + 2 * D_MLP, 0, 0, 1);
    launch_gemm(hbuf, mlp_w2 + (size_t)2 * D_MLP * D_MODEL, out_txt, L_TXT, D_MODEL, D_MLP,
                mlp_b2 + 2 * 1024, mod + 2 * 6144 + 5120, x1 + off_txt, 2);
}

// round 3
// speedup vs baseline: 1.6597x; 1.6597x over previous
#include <cuda_runtime.h>
#include <cuda_bf16.h>
#include <math.h>
#include <stdint.h>

// ---------------- problem constants ----------------
#define L_TXT 256
#define L_IMG 1024
#define L_TMP 1024
#define L_ALL 2304          // txt + img + tmp
#define D_MODEL 1024
#define NH 16
#define HD 64
#define D_MLP 4096
#define EPS 1e-6f
#define ATTN_SCALE 0.125f   // 1/sqrt(64)

// ---------------- scratch (static device memory; no allocation) ----------------
__device__ float g_sv[D_MODEL];
__device__ float g_mod[3 * 6144];
__device__ float g_xm[L_ALL * D_MODEL];        // LN1-modulated, concat order [txt|img|tmp]
__device__ float g_qkv[L_ALL * 3 * D_MODEL];   // QKV gemm out, same row order
__device__ float g_Q[NH * L_ALL * HD];
__device__ float g_K[NH * L_ALL * HD];
__device__ float g_V[NH * L_ALL * HD];
__device__ float g_attn[L_ALL * D_MODEL];      // [l][h*64+d], concat order
__device__ float g_x1[L_ALL * D_MODEL];        // post-proj residual, concat order
__device__ float g_ym[1024 * D_MODEL];         // LN2-modulated (per-stream reuse)
__device__ float g_h[1024 * D_MLP];            // MLP hidden (per-stream reuse)

// ---------------- helpers ----------------
__device__ __forceinline__ float gelu_tanh(float x) {
    const float c = 0.7978845608028654f; // sqrt(2/pi)
    float x3 = x * x * x;
    return 0.5f * x * (1.f + tanhf(c * (x + 0.044715f * x3)));
}

__device__ __forceinline__ uint32_t f2tf32(float f) {
    uint32_t u;
    asm("cvt.rna.tf32.f32 %0, %1;" : "=r"(u) : "f"(f));
    return u;
}

// ---------------- silu(vec) ----------------
__global__ void silu_kernel(const float* __restrict__ v, float* __restrict__ sv) {
    int t = threadIdx.x;
    float x = v[t];
    sv[t] = x / (1.f + expf(-x));
}

// ---------------- mod = sv @ mod_w + mod_b  (3 x 6144 outputs) ----------------
__global__ void mod_kernel(const float* __restrict__ sv, const float* __restrict__ mod_w,
                           const float* __restrict__ mod_b, float* __restrict__ mod) {
    __shared__ float s_sv[D_MODEL];
    for (int i = threadIdx.x; i < D_MODEL; i += 256) s_sv[i] = sv[i];
    __syncthreads();
    int o = blockIdx.x * 256 + threadIdx.x;       // 0 .. 3*6144-1
    int i = o / 6144;
    int j = o - i * 6144;
    const float* w = mod_w + (size_t)i * D_MODEL * 6144 + j;
    float acc = 0.f;
    #pragma unroll 8
    for (int d = 0; d < D_MODEL; ++d) acc = fmaf(s_sv[d], w[(size_t)d * 6144], acc);
    mod[o] = acc + mod_b[o];
}

// ---------------- LN + modulate: out = (1+sc)*ln(x) + sh ----------------
__global__ void lnmod_kernel(const float* __restrict__ x, float* __restrict__ out,
                             const float* __restrict__ sh, const float* __restrict__ sc) {
    int r = blockIdx.x;
    const float* xr = x + (size_t)r * D_MODEL;
    int t = threadIdx.x; // 256
    float v[4]; float sum = 0.f, sq = 0.f;
    #pragma unroll
    for (int i = 0; i < 4; i++) { float f = xr[t + i * 256]; v[i] = f; sum += f; sq += f * f; }
    #pragma unroll
    for (int o = 16; o; o >>= 1) {
        sum += __shfl_xor_sync(0xffffffffu, sum, o);
        sq  += __shfl_xor_sync(0xffffffffu, sq, o);
    }
    __shared__ float ssum[8], ssq[8];
    int w = t >> 5, lane = t & 31;
    if (lane == 0) { ssum[w] = sum; ssq[w] = sq; }
    __syncthreads();
    if (t == 0) {
        float S = 0.f, Q = 0.f;
        #pragma unroll
        for (int i = 0; i < 8; i++) { S += ssum[i]; Q += ssq[i]; }
        float mean = S * (1.f / D_MODEL);
        float var  = Q * (1.f / D_MODEL) - mean * mean;
        ssum[0] = mean; ssq[0] = rsqrtf(var + EPS);
    }
    __syncthreads();
    float mean = ssum[0], inv = ssq[0];
    float* orow = out + (size_t)r * D_MODEL;
    #pragma unroll
    for (int i = 0; i < 4; i++) {
        int d = t + i * 256;
        orow[d] = (1.f + sc[d]) * ((v[i] - mean) * inv) + sh[d];
    }
}

// ---------------- tf32 tensor-core GEMM: C = A(MxK) @ B(KxN) ----------------
// epi 0: C = acc
// epi 1: C = gelu(acc + bias[col])
// epi 2: C = res[row][col] + gate[col] * (acc + bias[col])
// Tiles: block 128x128x16, 8 warps (2x4), warp tile 64x32 via m16n8k8 mma.
#define TBM 128
#define TBN 128
#define TBK 16
#define LDA 132
#define LDB 132

__device__ __forceinline__ void mma_tf32(float& d0, float& d1, float& d2, float& d3,
                                         uint32_t a0, uint32_t a1, uint32_t a2, uint32_t a3,
                                         uint32_t b0, uint32_t b1) {
    asm volatile(
        "mma.sync.aligned.m16n8k8.row.col.f32.tf32.tf32.f32 "
        "{%0,%1,%2,%3}, {%4,%5,%6,%7}, {%8,%9}, {%0,%1,%2,%3};"
        : "+f"(d0), "+f"(d1), "+f"(d2), "+f"(d3)
        : "r"(a0), "r"(a1), "r"(a2), "r"(a3), "r"(b0), "r"(b1));
}

__global__ void __launch_bounds__(256) gemm_tc_kernel(
        const float* __restrict__ A, const float* __restrict__ B,
        float* __restrict__ C, int M, int N, int K,
        const float* __restrict__ bias,
        const float* __restrict__ gate,
        const float* __restrict__ res,
        int epi) {
    __shared__ uint32_t As[2][TBK][LDA];
    __shared__ uint32_t Bs[2][TBK][LDB];

    int tid  = threadIdx.x;
    int warp = tid >> 5;
    int lane = tid & 31;
    int gid  = lane >> 2;    // group id (0..7)
    int tig  = lane & 3;     // thread in group (0..3)
    int wm   = (warp >> 2) * 64;   // warp row offset in tile (0 or 64)
    int wn   = (warp & 3) * 32;    // warp col offset (0..96)

    int brow = blockIdx.y, bcol = blockIdx.x;

    // global load mapping
    int a_row = tid >> 1;              // 0..127
    int a_k   = (tid & 1) * 8;         // 0 or 8
    int b_row = tid >> 6;              // 0..3 (plus +4, +8, +12)
    int b_col = (tid & 63) * 2;        // 0..126, float2 granularity

    const float* Aptr = A + (size_t)(brow * TBM + a_row) * K + a_k;
    const float* Bptr = B + (size_t)b_row * N + bcol * TBN + b_col;

    float acc[4][4][4];
    #pragma unroll
    for (int i = 0; i < 4; i++)
        #pragma unroll
        for (int j = 0; j < 4; j++)
            #pragma unroll
            for (int c = 0; c < 4; c++) acc[i][j][c] = 0.f;

    int iters = K / TBK;

    // prefetch tile 0
    float4 av0 = *(const float4*)(Aptr);
    float4 av1 = *(const float4*)(Aptr + 4);
    float2 bv[4];
    #pragma unroll
    for (int r = 0; r < 4; r++)
        bv[r] = *(const float2*)(Bptr + (size_t)(r * 4) * N);

    // store tile 0
    {
        As[0][a_k + 0][a_row] = f2tf32(av0.x);
        As[0][a_k + 1][a_row] = f2tf32(av0.y);
        As[0][a_k + 2][a_row] = f2tf32(av0.z);
        As[0][a_k + 3][a_row] = f2tf32(av0.w);
        As[0][a_k + 4][a_row] = f2tf32(av1.x);
        As[0][a_k + 5][a_row] = f2tf32(av1.y);
        As[0][a_k + 6][a_row] = f2tf32(av1.z);
        As[0][a_k + 7][a_row] = f2tf32(av1.w);
        #pragma unroll
        for (int r = 0; r < 4; r++) {
            Bs[0][b_row + r * 4][b_col]     = f2tf32(bv[r].x);
            Bs[0][b_row + r * 4][b_col + 1] = f2tf32(bv[r].y);
        }
    }
    __syncthreads();

    for (int it = 0; it < iters; ++it) {
        int cur = it & 1;
        // prefetch next tile into registers
        if (it + 1 < iters) {
            int k0 = (it + 1) * TBK;
            av0 = *(const float4*)(Aptr + k0);
            av1 = *(const float4*)(Aptr + k0 + 4);
            #pragma unroll
            for (int r = 0; r < 4; r++)
                bv[r] = *(const float2*)(Bptr + (size_t)(k0 + r * 4) * N);
        }

        // compute from smem[cur]
        #pragma unroll
        for (int kk = 0; kk < TBK; kk += 8) {
            uint32_t af[4][4];
            #pragma unroll
            for (int mt = 0; mt < 4; mt++) {
                int m = wm + mt * 16 + gid;
                af[mt][0] = As[cur][kk + tig][m];
                af[mt][1] = As[cur][kk + tig][m + 8];
                af[mt][2] = As[cur][kk + tig + 4][m];
                af[mt][3] = As[cur][kk + tig + 4][m + 8];
            }
            uint32_t bf[4][2];
            #pragma unroll
            for (int nt = 0; nt < 4; nt++) {
                int n = wn + nt * 8 + gid;
                bf[nt][0] = Bs[cur][kk + tig][n];
                bf[nt][1] = Bs[cur][kk + tig + 4][n];
            }
            #pragma unroll
            for (int mt = 0; mt < 4; mt++)
                #pragma unroll
                for (int nt = 0; nt < 4; nt++)
                    mma_tf32(acc[mt][nt][0], acc[mt][nt][1], acc[mt][nt][2], acc[mt][nt][3],
                             af[mt][0], af[mt][1], af[mt][2], af[mt][3],
                             bf[nt][0], bf[nt][1]);
        }

        // store next tile
        if (it + 1 < iters) {
            int nxt = cur ^ 1;
            As[nxt][a_k + 0][a_row] = f2tf32(av0.x);
            As[nxt][a_k + 1][a_row] = f2tf32(av0.y);
            As[nxt][a_k + 2][a_row] = f2tf32(av0.z);
            As[nxt][a_k + 3][a_row] = f2tf32(av0.w);
            As[nxt][a_k + 4][a_row] = f2tf32(av1.x);
            As[nxt][a_k + 5][a_row] = f2tf32(av1.y);
            As[nxt][a_k + 6][a_row] = f2tf32(av1.z);
            As[nxt][a_k + 7][a_row] = f2tf32(av1.w);
            #pragma unroll
            for (int r = 0; r < 4; r++) {
                Bs[nxt][b_row + r * 4][b_col]     = f2tf32(bv[r].x);
                Bs[nxt][b_row + r * 4][b_col + 1] = f2tf32(bv[r].y);
            }
            __syncthreads();
        }
    }

    // epilogue
    #pragma unroll
    for (int mt = 0; mt < 4; mt++) {
        int row0 = brow * TBM + wm + mt * 16 + gid;
        int row1 = row0 + 8;
        #pragma unroll
        for (int nt = 0; nt < 4; nt++) {
            int col0 = bcol * TBN + wn + nt * 8 + tig * 2;
            int col1 = col0 + 1;
            float v0 = acc[mt][nt][0], v1 = acc[mt][nt][1];
            float v2 = acc[mt][nt][2], v3 = acc[mt][nt][3];
            if (epi == 1) {
                v0 = gelu_tanh(v0 + bias[col0]); v1 = gelu_tanh(v1 + bias[col1]);
                v2 = gelu_tanh(v2 + bias[col0]); v3 = gelu_tanh(v3 + bias[col1]);
            } else if (epi == 2) {
                v0 = res[(size_t)row0 * N + col0] + gate[col0] * (v0 + bias[col0]);
                v1 = res[(size_t)row0 * N + col1] + gate[col1] * (v1 + bias[col1]);
                v2 = res[(size_t)row1 * N + col0] + gate[col0] * (v2 + bias[col0]);
                v3 = res[(size_t)row1 * N + col1] + gate[col1] * (v3 + bias[col1]);
            }
            C[(size_t)row0 * N + col0] = v0;
            C[(size_t)row0 * N + col1] = v1;
            C[(size_t)row1 * N + col0] = v2;
            C[(size_t)row1 * N + col1] = v3;
        }
    }
}

// ---------------- QKV post: RMS + scale + RoPE + scatter to head-major ----------------
// Reference quirks replicated:
//   * V for the temporal rows (l >= 1280) is the RMS'd+scaled q BEFORE RoPE
//   * stream map (concat order): l<256 -> txt(stream 2), l<1280 -> img(0), else tmp(1)
__global__ void qkvpost_kernel(const float* __restrict__ Y, const float* __restrict__ pe,
                               const float* __restrict__ q_scale, const float* __restrict__ k_scale,
                               float* __restrict__ Q, float* __restrict__ K, float* __restrict__ V) {
    int gw = blockIdx.x * 8 + (threadIdx.x >> 5);   // warp id: 0 .. 2304*16-1
    int lane = threadIdx.x & 31;
    int l = gw >> 4;
    int h = gw & 15;
    int i = (l < L_TXT) ? 2 : (l < (L_TXT + L_IMG) ? 0 : 1);
    bool is_tmp = (l >= L_TXT + L_IMG);

    const float* row = Y + (size_t)l * 3072 + h * HD;
    float q0 = row[2 * lane],        q1 = row[2 * lane + 1];
    float k0 = row[1024 + 2 * lane], k1 = row[1024 + 2 * lane + 1];
    float v0 = row[2048 + 2 * lane], v1 = row[2048 + 2 * lane + 1];

    float qs = q0 * q0 + q1 * q1;
    float ks = k0 * k0 + k1 * k1;
    #pragma unroll
    for (int o = 16; o; o >>= 1) {
        qs += __shfl_xor_sync(0xffffffffu, qs, o);
        ks += __shfl_xor_sync(0xffffffffu, ks, o);
    }
    float qinv = rsqrtf(qs * (1.f / HD) + EPS);
    float kinv = rsqrtf(ks * (1.f / HD) + EPS);

    float qn0 = q0 * qinv * q_scale[i * HD + 2 * lane];
    float qn1 = q1 * qinv * q_scale[i * HD + 2 * lane + 1];
    float kn0 = k0 * kinv * k_scale[i * HD + 2 * lane];
    float kn1 = k1 * kinv * k_scale[i * HD + 2 * lane + 1];

    // pe[l][dd=lane][j][c], index = ((l*32+dd)*2 + j)*2 + c
    const float* p = pe + ((size_t)l * 32 + lane) * 4;
    float p00 = p[0], p01 = p[1], p10 = p[2], p11 = p[3];

    size_t base = ((size_t)h * L_ALL + l) * HD + 2 * lane;
    Q[base]     = p00 * qn0 + p01 * qn1;
    Q[base + 1] = p10 * qn0 + p11 * qn1;
    K[base]     = p00 * kn0 + p01 * kn1;
    K[base + 1] = p10 * kn0 + p11 * kn1;
    if (is_tmp) { V[base] = qn0; V[base + 1] = qn1; }
    else        { V[base] = v0;  V[base + 1] = v1;  }
}

// ---------------- flash attention (fp32): 64 q-rows/block, 32-key tiles ----------------
#define AQ 64
#define AK 32
__global__ void attn_kernel(const float* __restrict__ Q, const float* __restrict__ K,
                            const float* __restrict__ V, float* __restrict__ Aout) {
    __shared__ float Qs[AQ][65];
    __shared__ float Ks[AK][65];
    __shared__ float Vs[AK][65];
    __shared__ float Ps[AQ][33];

    int h  = blockIdx.y;
    int q0 = blockIdx.x * AQ;
    int tid = threadIdx.x;           // 256
    int qr = tid >> 2;               // 0..63
    int part = tid & 3;              // 0..3

    const float* Qh = Q + (size_t)h * L_ALL * HD;
    const float* Kh = K + (size_t)h * L_ALL * HD;
    const float* Vh = V + (size_t)h * L_ALL * HD;

    for (int idx = tid; idx < AQ * HD; idx += 256) {
        int r = idx >> 6, d = idx & 63;
        Qs[r][d] = Qh[(size_t)(q0 + r) * HD + d];
    }
    float m = -INFINITY, lsum = 0.f;
    float o[16];
    #pragma unroll
    for (int i = 0; i < 16; i++) o[i] = 0.f;
    __syncthreads();

    for (int k0 = 0; k0 < L_ALL; k0 += AK) {
        for (int idx = tid; idx < AK * HD; idx += 256) {
            int r = idx >> 6, d = idx & 63;
            Ks[r][d] = Kh[(size_t)(k0 + r) * HD + d];
            Vs[r][d] = Vh[(size_t)(k0 + r) * HD + d];
        }
        __syncthreads();

        float s[8];
        #pragma unroll
        for (int j = 0; j < 8; j++) {
            int kk = part * 8 + j;
            float acc = 0.f;
            #pragma unroll
            for (int d = 0; d < HD; d++) acc = fmaf(Qs[qr][d], Ks[kk][d], acc);
            s[j] = acc * ATTN_SCALE;
        }
        float tmax = s[0];
        #pragma unroll
        for (int j = 1; j < 8; j++) tmax = fmaxf(tmax, s[j]);
        tmax = fmaxf(tmax, __shfl_xor_sync(0xffffffffu, tmax, 1));
        tmax = fmaxf(tmax, __shfl_xor_sync(0xffffffffu, tmax, 2));
        float mnew = fmaxf(m, tmax);
        float alpha = __expf(m - mnew);
        float tsum = 0.f;
        #pragma unroll
        for (int j = 0; j < 8; j++) {
            float pv = __expf(s[j] - mnew);
            Ps[qr][part * 8 + j] = pv;
            tsum += pv;
        }
        tsum += __shfl_xor_sync(0xffffffffu, tsum, 1);
        tsum += __shfl_xor_sync(0xffffffffu, tsum, 2);
        lsum = lsum * alpha + tsum;
        m = mnew;
        #pragma unroll
        for (int i = 0; i < 16; i++) o[i] *= alpha;
        __syncthreads();
        #pragma unroll
        for (int kk = 0; kk < AK; kk++) {
            float pv = Ps[qr][kk];
            #pragma unroll
            for (int i = 0; i < 16; i++)
                o[i] = fmaf(pv, Vs[kk][part * 16 + i], o[i]);
        }
        __syncthreads();
    }

    float inv = 1.f / lsum;
    int l = q0 + qr;
    float* out = Aout + (size_t)l * D_MODEL + h * HD + part * 16;
    #pragma unroll
    for (int i = 0; i < 16; i++) out[i] = o[i] * inv;
}

// ---------------- host launch ----------------
static void launch_gemm(const float* A, const float* B, float* C, int M, int N, int K,
                        const float* bias, const float* gate, const float* res, int epi) {
    dim3 grid(N / TBN, M / TBM);
    gemm_tc_kernel<<<grid, 256>>>(A, B, C, M, N, K, bias, gate, res, epi);
}

extern "C" void kernel_launch(void* const* d_in, const int* in_sizes, int n_in,
                              void* d_out, int out_size) {
    const float* img      = (const float*)d_in[0];
    const float* temporal = (const float*)d_in[1];
    const float* txt      = (const float*)d_in[2];
    const float* vec      = (const float*)d_in[3];
    const float* pe       = (const float*)d_in[4];
    const float* mod_w    = (const float*)d_in[5];
    const float* mod_b    = (const float*)d_in[6];
    const float* qkv_w    = (const float*)d_in[7];
    const float* q_scale  = (const float*)d_in[8];
    const float* k_scale  = (const float*)d_in[9];
    const float* proj_w   = (const float*)d_in[10];
    const float* proj_b   = (const float*)d_in[11];
    const float* mlp_w1   = (const float*)d_in[12];
    const float* mlp_b1   = (const float*)d_in[13];
    const float* mlp_w2   = (const float*)d_in[14];
    const float* mlp_b2   = (const float*)d_in[15];
    float* out = (float*)d_out;
    float* out_img = out;
    float* out_tmp = out + (size_t)L_IMG * D_MODEL;
    float* out_txt = out + (size_t)(L_IMG + L_TMP) * D_MODEL;

    // Cache scratch addresses on first (non-captured, correctness) call so that
    // the captured call contains kernel launches ONLY.
    static float *sv = 0, *mod = 0, *xm = 0, *qkv = 0, *Qb = 0, *Kb = 0, *Vb = 0,
                 *attn = 0, *x1 = 0, *ym = 0, *hbuf = 0;
    if (!sv) {
        cudaGetSymbolAddress((void**)&sv,   g_sv);
        cudaGetSymbolAddress((void**)&mod,  g_mod);
        cudaGetSymbolAddress((void**)&xm,   g_xm);
        cudaGetSymbolAddress((void**)&qkv,  g_qkv);
        cudaGetSymbolAddress((void**)&Qb,   g_Q);
        cudaGetSymbolAddress((void**)&Kb,   g_K);
        cudaGetSymbolAddress((void**)&Vb,   g_V);
        cudaGetSymbolAddress((void**)&attn, g_attn);
        cudaGetSymbolAddress((void**)&x1,   g_x1);
        cudaGetSymbolAddress((void**)&ym,   g_ym);
        cudaGetSymbolAddress((void**)&hbuf, g_h);
    }

    // concat-order row offsets (rows of 1024 floats)
    const size_t off_txt = 0;
    const size_t off_img = (size_t)L_TXT * D_MODEL;
    const size_t off_tmp = (size_t)(L_TXT + L_IMG) * D_MODEL;

    // 1. sv = silu(vec)
    silu_kernel<<<1, 1024>>>(vec, sv);
    // 2. mod = sv @ mod_w + mod_b
    mod_kernel<<<(3 * 6144) / 256, 256>>>(sv, mod_w, mod_b, mod);

    // 3. LN1 + modulate (per stream; concat order txt|img|tmp)
    lnmod_kernel<<<L_TXT, 256>>>(txt,      xm + off_txt, mod + 2 * 6144,        mod + 2 * 6144 + 1024);
    lnmod_kernel<<<L_IMG, 256>>>(img,      xm + off_img, mod + 0,               mod + 1024);
    lnmod_kernel<<<L_TMP, 256>>>(temporal, xm + off_tmp, mod + 1 * 6144,        mod + 1 * 6144 + 1024);

    // 4. QKV GEMMs (per-stream weights)
    launch_gemm(xm + off_txt, qkv_w + (size_t)2 * D_MODEL * 3072, qkv + (size_t)0 * 3072,    L_TXT, 3072, D_MODEL, 0, 0, 0, 0);
    launch_gemm(xm + off_img, qkv_w + (size_t)0 * D_MODEL * 3072, qkv + (size_t)L_TXT * 3072, L_IMG, 3072, D_MODEL, 0, 0, 0, 0);
    launch_gemm(xm + off_tmp, qkv_w + (size_t)1 * D_MODEL * 3072, qkv + (size_t)(L_TXT + L_IMG) * 3072, L_TMP, 3072, D_MODEL, 0, 0, 0, 0);

    // 5. RMS + scale + RoPE + scatter (and the v<-tmp_q quirk)
    qkvpost_kernel<<<(L_ALL * NH) / 8, 256>>>(qkv, pe, q_scale, k_scale, Qb, Kb, Vb);

    // 6. attention
    attn_kernel<<<dim3(L_ALL / AQ, NH), 256>>>(Qb, Kb, Vb, attn);

    // 7. proj + gate + residual -> x1 (per stream)
    launch_gemm(attn + off_txt, proj_w + (size_t)2 * D_MODEL * D_MODEL, x1 + off_txt, L_TXT, D_MODEL, D_MODEL,
                proj_b + 2 * 1024, mod + 2 * 6144 + 2048, txt, 2);
    launch_gemm(attn + off_img, proj_w + (size_t)0,                     x1 + off_img, L_IMG, D_MODEL, D_MODEL,
                proj_b + 0,        mod + 0 * 6144 + 2048, img, 2);
    launch_gemm(attn + off_tmp, proj_w + (size_t)1 * D_MODEL * D_MODEL, x1 + off_tmp, L_TMP, D_MODEL, D_MODEL,
                proj_b + 1 * 1024, mod + 1 * 6144 + 2048, temporal, 2);

    // 8. img MLP (must finish before temporal's LN-of-final-img)
    lnmod_kernel<<<L_IMG, 256>>>(x1 + off_img, ym, mod + 0 * 6144 + 3072, mod + 0 * 6144 + 4096);
    launch_gemm(ym, mlp_w1 + (size_t)0, hbuf, L_IMG, D_MLP, D_MODEL, mlp_b1 + 0, 0, 0, 1);
    launch_gemm(hbuf, mlp_w2 + (size_t)0, out_img, L_IMG, D_MODEL, D_MLP,
                mlp_b2 + 0, mod + 0 * 6144 + 5120, x1 + off_img, 2);

    // 9. temporal MLP: LN of FINAL img (reference quirk), residual = x1_tmp
    lnmod_kernel<<<L_TMP, 256>>>(out_img, ym, mod + 1 * 6144 + 3072, mod + 1 * 6144 + 4096);
    launch_gemm(ym, mlp_w1 + (size_t)1 * D_MODEL * D_MLP, hbuf, L_TMP, D_MLP, D_MODEL, mlp_b1 + D_MLP, 0, 0, 1);
    launch_gemm(hbuf, mlp_w2 + (size_t)1 * D_MLP * D_MODEL, out_tmp, L_TMP, D_MODEL, D_MLP,
                mlp_b2 + 1024, mod + 1 * 6144 + 5120, x1 + off_tmp, 2);

    // 10. txt MLP
    lnmod_kernel<<<L_TXT, 256>>>(x1 + off_txt, ym, mod + 2 * 6144 + 3072, mod + 2 * 6144 + 4096);
    launch_gemm(ym, mlp_w1 + (size_t)2 * D_MODEL * D_MLP, hbuf, L_TXT, D_MLP, D_MODEL, mlp_b1 + 2 * D_MLP, 0, 0, 1);
    launch_gemm(hbuf, mlp_w2 + (size_t)2 * D_MLP * D_MODEL, out_txt, L_TXT, D_MODEL, D_MLP,
                mlp_b2 + 2 * 1024, mod + 2 * 6144 + 5120, x1 + off_txt, 2);
}

// round 4
// speedup vs baseline: 3.4310x; 2.0673x over previous
#include <cuda_runtime.h>
#include <cuda_bf16.h>
#include <math.h>
#include <stdint.h>

// ---------------- problem constants ----------------
#define L_TXT 256
#define L_IMG 1024
#define L_TMP 1024
#define L_ALL 2304          // txt + img + tmp
#define D_MODEL 1024
#define NH 16
#define HD 64
#define D_MLP 4096
#define EPS 1e-6f
#define ATTN_SCALE 0.125f   // 1/sqrt(64)

// ---------------- scratch (static device memory; no allocation) ----------------
__device__ float g_sv[D_MODEL];
__device__ float g_mod[3 * 6144];
__device__ float g_xm[L_ALL * D_MODEL];        // LN1-modulated, concat order [txt|img|tmp]
__device__ float g_qkv[L_ALL * 3 * D_MODEL];   // QKV gemm out, same row order
__device__ float g_Q[NH * L_ALL * HD];
__device__ float g_K[NH * L_ALL * HD];
__device__ float g_V[NH * L_ALL * HD];
__device__ float g_attn[L_ALL * D_MODEL];      // [l][h*64+d], concat order
__device__ float g_x1[L_ALL * D_MODEL];        // post-proj residual, concat order
__device__ float g_ym[1024 * D_MODEL];         // LN2-modulated (per-stream reuse)
__device__ float g_h[1024 * D_MLP];            // MLP hidden (per-stream reuse)

// ---------------- helpers ----------------
__device__ __forceinline__ float gelu_tanh(float x) {
    const float c = 0.7978845608028654f; // sqrt(2/pi)
    float x3 = x * x * x;
    return 0.5f * x * (1.f + tanhf(c * (x + 0.044715f * x3)));
}

__device__ __forceinline__ uint32_t f2tf32(float f) {
    uint32_t u;
    asm("cvt.rna.tf32.f32 %0, %1;" : "=r"(u) : "f"(f));
    return u;
}

__device__ __forceinline__ void mma_tf32(float& d0, float& d1, float& d2, float& d3,
                                         uint32_t a0, uint32_t a1, uint32_t a2, uint32_t a3,
                                         uint32_t b0, uint32_t b1) {
    asm volatile(
        "mma.sync.aligned.m16n8k8.row.col.f32.tf32.tf32.f32 "
        "{%0,%1,%2,%3}, {%4,%5,%6,%7}, {%8,%9}, {%0,%1,%2,%3};"
        : "+f"(d0), "+f"(d1), "+f"(d2), "+f"(d3)
        : "r"(a0), "r"(a1), "r"(a2), "r"(a3), "r"(b0), "r"(b1));
}

// ---------------- silu(vec) ----------------
__global__ void silu_kernel(const float* __restrict__ v, float* __restrict__ sv) {
    int t = threadIdx.x;
    float x = v[t];
    sv[t] = x / (1.f + expf(-x));
}

// ---------------- mod = sv @ mod_w + mod_b  (3 x 6144 outputs) ----------------
__global__ void mod_kernel(const float* __restrict__ sv, const float* __restrict__ mod_w,
                           const float* __restrict__ mod_b, float* __restrict__ mod) {
    __shared__ float s_sv[D_MODEL];
    for (int i = threadIdx.x; i < D_MODEL; i += 256) s_sv[i] = sv[i];
    __syncthreads();
    int o = blockIdx.x * 256 + threadIdx.x;       // 0 .. 3*6144-1
    int i = o / 6144;
    int j = o - i * 6144;
    const float* w = mod_w + (size_t)i * D_MODEL * 6144 + j;
    float acc = 0.f;
    #pragma unroll 8
    for (int d = 0; d < D_MODEL; ++d) acc = fmaf(s_sv[d], w[(size_t)d * 6144], acc);
    mod[o] = acc + mod_b[o];
}

// ---------------- LN + modulate: out = (1+sc)*ln(x) + sh ----------------
__global__ void lnmod_kernel(const float* __restrict__ x, float* __restrict__ out,
                             const float* __restrict__ sh, const float* __restrict__ sc) {
    int r = blockIdx.x;
    const float* xr = x + (size_t)r * D_MODEL;
    int t = threadIdx.x; // 256
    float v[4]; float sum = 0.f, sq = 0.f;
    #pragma unroll
    for (int i = 0; i < 4; i++) { float f = xr[t + i * 256]; v[i] = f; sum += f; sq += f * f; }
    #pragma unroll
    for (int o = 16; o; o >>= 1) {
        sum += __shfl_xor_sync(0xffffffffu, sum, o);
        sq  += __shfl_xor_sync(0xffffffffu, sq, o);
    }
    __shared__ float ssum[8], ssq[8];
    int w = t >> 5, lane = t & 31;
    if (lane == 0) { ssum[w] = sum; ssq[w] = sq; }
    __syncthreads();
    if (t == 0) {
        float S = 0.f, Q = 0.f;
        #pragma unroll
        for (int i = 0; i < 8; i++) { S += ssum[i]; Q += ssq[i]; }
        float mean = S * (1.f / D_MODEL);
        float var  = Q * (1.f / D_MODEL) - mean * mean;
        ssum[0] = mean; ssq[0] = rsqrtf(var + EPS);
    }
    __syncthreads();
    float mean = ssum[0], inv = ssq[0];
    float* orow = out + (size_t)r * D_MODEL;
    #pragma unroll
    for (int i = 0; i < 4; i++) {
        int d = t + i * 256;
        orow[d] = (1.f + sc[d]) * ((v[i] - mean) * inv) + sh[d];
    }
}

// ---------------- tf32 tensor-core GEMM: C = A(MxK) @ B(KxN) ----------------
#define TBM 128
#define TBN 128
#define TBK 16
#define LDA 132
#define LDB 132

__global__ void __launch_bounds__(256) gemm_tc_kernel(
        const float* __restrict__ A, const float* __restrict__ B,
        float* __restrict__ C, int M, int N, int K,
        const float* __restrict__ bias,
        const float* __restrict__ gate,
        const float* __restrict__ res,
        int epi) {
    __shared__ uint32_t As[2][TBK][LDA];
    __shared__ uint32_t Bs[2][TBK][LDB];

    int tid  = threadIdx.x;
    int warp = tid >> 5;
    int lane = tid & 31;
    int gid  = lane >> 2;    // group id (0..7)
    int tig  = lane & 3;     // thread in group (0..3)
    int wm   = (warp >> 2) * 64;   // warp row offset in tile (0 or 64)
    int wn   = (warp & 3) * 32;    // warp col offset (0..96)

    int brow = blockIdx.y, bcol = blockIdx.x;

    int a_row = tid >> 1;              // 0..127
    int a_k   = (tid & 1) * 8;         // 0 or 8
    int b_row = tid >> 6;              // 0..3 (plus +4, +8, +12)
    int b_col = (tid & 63) * 2;        // 0..126, float2 granularity

    const float* Aptr = A + (size_t)(brow * TBM + a_row) * K + a_k;
    const float* Bptr = B + (size_t)b_row * N + bcol * TBN + b_col;

    float acc[4][4][4];
    #pragma unroll
    for (int i = 0; i < 4; i++)
        #pragma unroll
        for (int j = 0; j < 4; j++)
            #pragma unroll
            for (int c = 0; c < 4; c++) acc[i][j][c] = 0.f;

    int iters = K / TBK;

    float4 av0 = *(const float4*)(Aptr);
    float4 av1 = *(const float4*)(Aptr + 4);
    float2 bv[4];
    #pragma unroll
    for (int r = 0; r < 4; r++)
        bv[r] = *(const float2*)(Bptr + (size_t)(r * 4) * N);

    {
        As[0][a_k + 0][a_row] = f2tf32(av0.x);
        As[0][a_k + 1][a_row] = f2tf32(av0.y);
        As[0][a_k + 2][a_row] = f2tf32(av0.z);
        As[0][a_k + 3][a_row] = f2tf32(av0.w);
        As[0][a_k + 4][a_row] = f2tf32(av1.x);
        As[0][a_k + 5][a_row] = f2tf32(av1.y);
        As[0][a_k + 6][a_row] = f2tf32(av1.z);
        As[0][a_k + 7][a_row] = f2tf32(av1.w);
        #pragma unroll
        for (int r = 0; r < 4; r++) {
            Bs[0][b_row + r * 4][b_col]     = f2tf32(bv[r].x);
            Bs[0][b_row + r * 4][b_col + 1] = f2tf32(bv[r].y);
        }
    }
    __syncthreads();

    for (int it = 0; it < iters; ++it) {
        int cur = it & 1;
        if (it + 1 < iters) {
            int k0 = (it + 1) * TBK;
            av0 = *(const float4*)(Aptr + k0);
            av1 = *(const float4*)(Aptr + k0 + 4);
            #pragma unroll
            for (int r = 0; r < 4; r++)
                bv[r] = *(const float2*)(Bptr + (size_t)(k0 + r * 4) * N);
        }

        #pragma unroll
        for (int kk = 0; kk < TBK; kk += 8) {
            uint32_t af[4][4];
            #pragma unroll
            for (int mt = 0; mt < 4; mt++) {
                int m = wm + mt * 16 + gid;
                af[mt][0] = As[cur][kk + tig][m];
                af[mt][1] = As[cur][kk + tig][m + 8];
                af[mt][2] = As[cur][kk + tig + 4][m];
                af[mt][3] = As[cur][kk + tig + 4][m + 8];
            }
            uint32_t bf[4][2];
            #pragma unroll
            for (int nt = 0; nt < 4; nt++) {
                int n = wn + nt * 8 + gid;
                bf[nt][0] = Bs[cur][kk + tig][n];
                bf[nt][1] = Bs[cur][kk + tig + 4][n];
            }
            #pragma unroll
            for (int mt = 0; mt < 4; mt++)
                #pragma unroll
                for (int nt = 0; nt < 4; nt++)
                    mma_tf32(acc[mt][nt][0], acc[mt][nt][1], acc[mt][nt][2], acc[mt][nt][3],
                             af[mt][0], af[mt][1], af[mt][2], af[mt][3],
                             bf[nt][0], bf[nt][1]);
        }

        if (it + 1 < iters) {
            int nxt = cur ^ 1;
            As[nxt][a_k + 0][a_row] = f2tf32(av0.x);
            As[nxt][a_k + 1][a_row] = f2tf32(av0.y);
            As[nxt][a_k + 2][a_row] = f2tf32(av0.z);
            As[nxt][a_k + 3][a_row] = f2tf32(av0.w);
            As[nxt][a_k + 4][a_row] = f2tf32(av1.x);
            As[nxt][a_k + 5][a_row] = f2tf32(av1.y);
            As[nxt][a_k + 6][a_row] = f2tf32(av1.z);
            As[nxt][a_k + 7][a_row] = f2tf32(av1.w);
            #pragma unroll
            for (int r = 0; r < 4; r++) {
                Bs[nxt][b_row + r * 4][b_col]     = f2tf32(bv[r].x);
                Bs[nxt][b_row + r * 4][b_col + 1] = f2tf32(bv[r].y);
            }
            __syncthreads();
        }
    }

    #pragma unroll
    for (int mt = 0; mt < 4; mt++) {
        int row0 = brow * TBM + wm + mt * 16 + gid;
        int row1 = row0 + 8;
        #pragma unroll
        for (int nt = 0; nt < 4; nt++) {
            int col0 = bcol * TBN + wn + nt * 8 + tig * 2;
            int col1 = col0 + 1;
            float v0 = acc[mt][nt][0], v1 = acc[mt][nt][1];
            float v2 = acc[mt][nt][2], v3 = acc[mt][nt][3];
            if (epi == 1) {
                v0 = gelu_tanh(v0 + bias[col0]); v1 = gelu_tanh(v1 + bias[col1]);
                v2 = gelu_tanh(v2 + bias[col0]); v3 = gelu_tanh(v3 + bias[col1]);
            } else if (epi == 2) {
                v0 = res[(size_t)row0 * N + col0] + gate[col0] * (v0 + bias[col0]);
                v1 = res[(size_t)row0 * N + col1] + gate[col1] * (v1 + bias[col1]);
                v2 = res[(size_t)row1 * N + col0] + gate[col0] * (v2 + bias[col0]);
                v3 = res[(size_t)row1 * N + col1] + gate[col1] * (v3 + bias[col1]);
            }
            C[(size_t)row0 * N + col0] = v0;
            C[(size_t)row0 * N + col1] = v1;
            C[(size_t)row1 * N + col0] = v2;
            C[(size_t)row1 * N + col1] = v3;
        }
    }
}

// ---------------- QKV post: RMS + scale + RoPE + scatter to head-major ----------------
__global__ void qkvpost_kernel(const float* __restrict__ Y, const float* __restrict__ pe,
                               const float* __restrict__ q_scale, const float* __restrict__ k_scale,
                               float* __restrict__ Q, float* __restrict__ K, float* __restrict__ V) {
    int gw = blockIdx.x * 8 + (threadIdx.x >> 5);   // warp id: 0 .. 2304*16-1
    int lane = threadIdx.x & 31;
    int l = gw >> 4;
    int h = gw & 15;
    int i = (l < L_TXT) ? 2 : (l < (L_TXT + L_IMG) ? 0 : 1);
    bool is_tmp = (l >= L_TXT + L_IMG);

    const float* row = Y + (size_t)l * 3072 + h * HD;
    float q0 = row[2 * lane],        q1 = row[2 * lane + 1];
    float k0 = row[1024 + 2 * lane], k1 = row[1024 + 2 * lane + 1];
    float v0 = row[2048 + 2 * lane], v1 = row[2048 + 2 * lane + 1];

    float qs = q0 * q0 + q1 * q1;
    float ks = k0 * k0 + k1 * k1;
    #pragma unroll
    for (int o = 16; o; o >>= 1) {
        qs += __shfl_xor_sync(0xffffffffu, qs, o);
        ks += __shfl_xor_sync(0xffffffffu, ks, o);
    }
    float qinv = rsqrtf(qs * (1.f / HD) + EPS);
    float kinv = rsqrtf(ks * (1.f / HD) + EPS);

    float qn0 = q0 * qinv * q_scale[i * HD + 2 * lane];
    float qn1 = q1 * qinv * q_scale[i * HD + 2 * lane + 1];
    float kn0 = k0 * kinv * k_scale[i * HD + 2 * lane];
    float kn1 = k1 * kinv * k_scale[i * HD + 2 * lane + 1];

    const float* p = pe + ((size_t)l * 32 + lane) * 4;
    float p00 = p[0], p01 = p[1], p10 = p[2], p11 = p[3];

    size_t base = ((size_t)h * L_ALL + l) * HD + 2 * lane;
    Q[base]     = p00 * qn0 + p01 * qn1;
    Q[base + 1] = p10 * qn0 + p11 * qn1;
    K[base]     = p00 * kn0 + p01 * kn1;
    K[base + 1] = p10 * kn0 + p11 * kn1;
    if (is_tmp) { V[base] = qn0; V[base + 1] = qn1; }
    else        { V[base] = v0;  V[base + 1] = v1;  }
}

// ---------------- flash attention on tensor cores (tf32 mma) ----------------
// Block: 1 head x 64 q-rows, 4 warps x 16 q-rows. 64-key tiles.
// smem (dynamic): Ks[64][68], Vs[64][68], Ps[64][68] (u32/tf32). Ps doubles as Q staging.
#define ATQ 64
#define ATK 64
#define ALD 68

__global__ void __launch_bounds__(128) attn_tc_kernel(
        const float* __restrict__ Q, const float* __restrict__ K,
        const float* __restrict__ V, float* __restrict__ Aout) {
    extern __shared__ uint32_t dyn[];
    uint32_t (*Ks)[ALD] = (uint32_t(*)[ALD])dyn;
    uint32_t (*Vs)[ALD] = (uint32_t(*)[ALD])(dyn + ATK * ALD);
    uint32_t (*Ps)[ALD] = (uint32_t(*)[ALD])(dyn + 2 * ATK * ALD);

    int h   = blockIdx.y;
    int q0  = blockIdx.x * ATQ;
    int tid = threadIdx.x;          // 128
    int warp = tid >> 5;            // 0..3 -> q rows [warp*16, warp*16+16)
    int lane = tid & 31;
    int gid  = lane >> 2;           // 0..7
    int tig  = lane & 3;            // 0..3
    int w16  = warp * 16;

    const float* Qh = Q + (size_t)h * L_ALL * HD;
    const float* Kh = K + (size_t)h * L_ALL * HD;
    const float* Vh = V + (size_t)h * L_ALL * HD;

    // stage Q (pre-scaled) into Ps, cooperative
    #pragma unroll
    for (int i = 0; i < 8; i++) {
        int linear = tid + i * 128;          // 0..1023 float4 slots
        int r = linear >> 4;                 // 64 rows
        int c4 = (linear & 15) * 4;          // 16 float4 per row
        float4 qv = *(const float4*)(Qh + (size_t)(q0 + r) * HD + c4);
        Ps[r][c4 + 0] = f2tf32(qv.x * ATTN_SCALE);
        Ps[r][c4 + 1] = f2tf32(qv.y * ATTN_SCALE);
        Ps[r][c4 + 2] = f2tf32(qv.z * ATTN_SCALE);
        Ps[r][c4 + 3] = f2tf32(qv.w * ATTN_SCALE);
    }
    __syncthreads();

    // Q fragments: 8 k-steps x 4 regs (warp-private rows)
    uint32_t qf[8][4];
    #pragma unroll
    for (int ks = 0; ks < 8; ks++) {
        qf[ks][0] = Ps[w16 + gid][ks * 8 + tig];
        qf[ks][1] = Ps[w16 + gid + 8][ks * 8 + tig];
        qf[ks][2] = Ps[w16 + gid][ks * 8 + tig + 4];
        qf[ks][3] = Ps[w16 + gid + 8][ks * 8 + tig + 4];
    }

    float oacc[8][4];
    #pragma unroll
    for (int nt = 0; nt < 8; nt++)
        #pragma unroll
        for (int c = 0; c < 4; c++) oacc[nt][c] = 0.f;
    float m0 = -INFINITY, m1 = -INFINITY, l0 = 0.f, l1 = 0.f;

    for (int kb = 0; kb < L_ALL; kb += ATK) {
        __syncthreads();   // previous iter done reading Ks/Vs (and Q staging read)
        // load K/V tile
        #pragma unroll
        for (int i = 0; i < 8; i++) {
            int linear = tid + i * 128;
            int r = linear >> 4;
            int c4 = (linear & 15) * 4;
            float4 kv = *(const float4*)(Kh + (size_t)(kb + r) * HD + c4);
            float4 vv = *(const float4*)(Vh + (size_t)(kb + r) * HD + c4);
            Ks[r][c4 + 0] = f2tf32(kv.x); Ks[r][c4 + 1] = f2tf32(kv.y);
            Ks[r][c4 + 2] = f2tf32(kv.z); Ks[r][c4 + 3] = f2tf32(kv.w);
            Vs[r][c4 + 0] = f2tf32(vv.x); Vs[r][c4 + 1] = f2tf32(vv.y);
            Vs[r][c4 + 2] = f2tf32(vv.z); Vs[r][c4 + 3] = f2tf32(vv.w);
        }
        __syncthreads();

        // S = Q @ K^T  (16 rows x 64 keys per warp)
        float sacc[8][4];
        #pragma unroll
        for (int nt = 0; nt < 8; nt++)
            #pragma unroll
            for (int c = 0; c < 4; c++) sacc[nt][c] = 0.f;
        #pragma unroll
        for (int ks = 0; ks < 8; ks++) {
            #pragma unroll
            for (int nt = 0; nt < 8; nt++) {
                uint32_t b0 = Ks[nt * 8 + gid][ks * 8 + tig];
                uint32_t b1 = Ks[nt * 8 + gid][ks * 8 + tig + 4];
                mma_tf32(sacc[nt][0], sacc[nt][1], sacc[nt][2], sacc[nt][3],
                         qf[ks][0], qf[ks][1], qf[ks][2], qf[ks][3], b0, b1);
            }
        }

        // online softmax. rows: r0 = gid, r1 = gid+8 (regs 0,1 / 2,3)
        float t0 = -INFINITY, t1 = -INFINITY;
        #pragma unroll
        for (int nt = 0; nt < 8; nt++) {
            t0 = fmaxf(t0, fmaxf(sacc[nt][0], sacc[nt][1]));
            t1 = fmaxf(t1, fmaxf(sacc[nt][2], sacc[nt][3]));
        }
        t0 = fmaxf(t0, __shfl_xor_sync(0xffffffffu, t0, 1));
        t0 = fmaxf(t0, __shfl_xor_sync(0xffffffffu, t0, 2));
        t1 = fmaxf(t1, __shfl_xor_sync(0xffffffffu, t1, 1));
        t1 = fmaxf(t1, __shfl_xor_sync(0xffffffffu, t1, 2));
        float mn0 = fmaxf(m0, t0), mn1 = fmaxf(m1, t1);
        float al0 = __expf(m0 - mn0), al1 = __expf(m1 - mn1);
        m0 = mn0; m1 = mn1;

        float ts0 = 0.f, ts1 = 0.f;
        #pragma unroll
        for (int nt = 0; nt < 8; nt++) {
            int c0 = nt * 8 + tig * 2;
            uint32_t p00 = f2tf32(__expf(sacc[nt][0] - mn0));
            uint32_t p01 = f2tf32(__expf(sacc[nt][1] - mn0));
            uint32_t p10 = f2tf32(__expf(sacc[nt][2] - mn1));
            uint32_t p11 = f2tf32(__expf(sacc[nt][3] - mn1));
            Ps[w16 + gid][c0]         = p00;
            Ps[w16 + gid][c0 + 1]     = p01;
            Ps[w16 + gid + 8][c0]     = p10;
            Ps[w16 + gid + 8][c0 + 1] = p11;
            ts0 += __uint_as_float(p00) + __uint_as_float(p01);
            ts1 += __uint_as_float(p10) + __uint_as_float(p11);
        }
        ts0 += __shfl_xor_sync(0xffffffffu, ts0, 1);
        ts0 += __shfl_xor_sync(0xffffffffu, ts0, 2);
        ts1 += __shfl_xor_sync(0xffffffffu, ts1, 1);
        ts1 += __shfl_xor_sync(0xffffffffu, ts1, 2);
        l0 = l0 * al0 + ts0;
        l1 = l1 * al1 + ts1;

        #pragma unroll
        for (int nt = 0; nt < 8; nt++) {
            oacc[nt][0] *= al0; oacc[nt][1] *= al0;
            oacc[nt][2] *= al1; oacc[nt][3] *= al1;
        }
        __syncwarp();   // Ps rows are warp-private; warp-level ordering suffices

        // O += P @ V  (16 rows x 64 d per warp; k = 64 keys)
        #pragma unroll
        for (int ks = 0; ks < 8; ks++) {
            uint32_t a0 = Ps[w16 + gid][ks * 8 + tig];
            uint32_t a1 = Ps[w16 + gid + 8][ks * 8 + tig];
            uint32_t a2 = Ps[w16 + gid][ks * 8 + tig + 4];
            uint32_t a3 = Ps[w16 + gid + 8][ks * 8 + tig + 4];
            #pragma unroll
            for (int nt = 0; nt < 8; nt++) {
                uint32_t b0 = Vs[ks * 8 + tig][nt * 8 + gid];
                uint32_t b1 = Vs[ks * 8 + tig + 4][nt * 8 + gid];
                mma_tf32(oacc[nt][0], oacc[nt][1], oacc[nt][2], oacc[nt][3],
                         a0, a1, a2, a3, b0, b1);
            }
        }
        __syncwarp();
    }

    float i0 = 1.f / l0, i1 = 1.f / l1;
    int r0 = q0 + w16 + gid;
    int r1 = r0 + 8;
    #pragma unroll
    for (int nt = 0; nt < 8; nt++) {
        int c0 = h * HD + nt * 8 + tig * 2;
        Aout[(size_t)r0 * D_MODEL + c0]     = oacc[nt][0] * i0;
        Aout[(size_t)r0 * D_MODEL + c0 + 1] = oacc[nt][1] * i0;
        Aout[(size_t)r1 * D_MODEL + c0]     = oacc[nt][2] * i1;
        Aout[(size_t)r1 * D_MODEL + c0 + 1] = oacc[nt][3] * i1;
    }
}

#define ATTN_SMEM (3 * ATK * ALD * 4)

// ---------------- host launch ----------------
static void launch_gemm(const float* A, const float* B, float* C, int M, int N, int K,
                        const float* bias, const float* gate, const float* res, int epi) {
    dim3 grid(N / TBN, M / TBM);
    gemm_tc_kernel<<<grid, 256>>>(A, B, C, M, N, K, bias, gate, res, epi);
}

extern "C" void kernel_launch(void* const* d_in, const int* in_sizes, int n_in,
                              void* d_out, int out_size) {
    const float* img      = (const float*)d_in[0];
    const float* temporal = (const float*)d_in[1];
    const float* txt      = (const float*)d_in[2];
    const float* vec      = (const float*)d_in[3];
    const float* pe       = (const float*)d_in[4];
    const float* mod_w    = (const float*)d_in[5];
    const float* mod_b    = (const float*)d_in[6];
    const float* qkv_w    = (const float*)d_in[7];
    const float* q_scale  = (const float*)d_in[8];
    const float* k_scale  = (const float*)d_in[9];
    const float* proj_w   = (const float*)d_in[10];
    const float* proj_b   = (const float*)d_in[11];
    const float* mlp_w1   = (const float*)d_in[12];
    const float* mlp_b1   = (const float*)d_in[13];
    const float* mlp_w2   = (const float*)d_in[14];
    const float* mlp_b2   = (const float*)d_in[15];
    float* out = (float*)d_out;
    float* out_img = out;
    float* out_tmp = out + (size_t)L_IMG * D_MODEL;
    float* out_txt = out + (size_t)(L_IMG + L_TMP) * D_MODEL;

    // One-time setup on the first (non-captured, correctness) call so that the
    // captured call contains kernel launches ONLY.
    static float *sv = 0, *mod = 0, *xm = 0, *qkv = 0, *Qb = 0, *Kb = 0, *Vb = 0,
                 *attn = 0, *x1 = 0, *ym = 0, *hbuf = 0;
    if (!sv) {
        cudaGetSymbolAddress((void**)&sv,   g_sv);
        cudaGetSymbolAddress((void**)&mod,  g_mod);
        cudaGetSymbolAddress((void**)&xm,   g_xm);
        cudaGetSymbolAddress((void**)&qkv,  g_qkv);
        cudaGetSymbolAddress((void**)&Qb,   g_Q);
        cudaGetSymbolAddress((void**)&Kb,   g_K);
        cudaGetSymbolAddress((void**)&Vb,   g_V);
        cudaGetSymbolAddress((void**)&attn, g_attn);
        cudaGetSymbolAddress((void**)&x1,   g_x1);
        cudaGetSymbolAddress((void**)&ym,   g_ym);
        cudaGetSymbolAddress((void**)&hbuf, g_h);
        cudaFuncSetAttribute(attn_tc_kernel,
                             cudaFuncAttributeMaxDynamicSharedMemorySize, ATTN_SMEM);
    }

    const size_t off_txt = 0;
    const size_t off_img = (size_t)L_TXT * D_MODEL;
    const size_t off_tmp = (size_t)(L_TXT + L_IMG) * D_MODEL;

    // 1. sv = silu(vec)
    silu_kernel<<<1, 1024>>>(vec, sv);
    // 2. mod = sv @ mod_w + mod_b
    mod_kernel<<<(3 * 6144) / 256, 256>>>(sv, mod_w, mod_b, mod);

    // 3. LN1 + modulate
    lnmod_kernel<<<L_TXT, 256>>>(txt,      xm + off_txt, mod + 2 * 6144,        mod + 2 * 6144 + 1024);
    lnmod_kernel<<<L_IMG, 256>>>(img,      xm + off_img, mod + 0,               mod + 1024);
    lnmod_kernel<<<L_TMP, 256>>>(temporal, xm + off_tmp, mod + 1 * 6144,        mod + 1 * 6144 + 1024);

    // 4. QKV GEMMs
    launch_gemm(xm + off_txt, qkv_w + (size_t)2 * D_MODEL * 3072, qkv + (size_t)0 * 3072,    L_TXT, 3072, D_MODEL, 0, 0, 0, 0);
    launch_gemm(xm + off_img, qkv_w + (size_t)0 * D_MODEL * 3072, qkv + (size_t)L_TXT * 3072, L_IMG, 3072, D_MODEL, 0, 0, 0, 0);
    launch_gemm(xm + off_tmp, qkv_w + (size_t)1 * D_MODEL * 3072, qkv + (size_t)(L_TXT + L_IMG) * 3072, L_TMP, 3072, D_MODEL, 0, 0, 0, 0);

    // 5. RMS + scale + RoPE + scatter
    qkvpost_kernel<<<(L_ALL * NH) / 8, 256>>>(qkv, pe, q_scale, k_scale, Qb, Kb, Vb);

    // 6. attention (tensor cores)
    attn_tc_kernel<<<dim3(L_ALL / ATQ, NH), 128, ATTN_SMEM>>>(Qb, Kb, Vb, attn);

    // 7. proj + gate + residual -> x1
    launch_gemm(attn + off_txt, proj_w + (size_t)2 * D_MODEL * D_MODEL, x1 + off_txt, L_TXT, D_MODEL, D_MODEL,
                proj_b + 2 * 1024, mod + 2 * 6144 + 2048, txt, 2);
    launch_gemm(attn + off_img, proj_w + (size_t)0,                     x1 + off_img, L_IMG, D_MODEL, D_MODEL,
                proj_b + 0,        mod + 0 * 6144 + 2048, img, 2);
    launch_gemm(attn + off_tmp, proj_w + (size_t)1 * D_MODEL * D_MODEL, x1 + off_tmp, L_TMP, D_MODEL, D_MODEL,
                proj_b + 1 * 1024, mod + 1 * 6144 + 2048, temporal, 2);

    // 8. img MLP
    lnmod_kernel<<<L_IMG, 256>>>(x1 + off_img, ym, mod + 0 * 6144 + 3072, mod + 0 * 6144 + 4096);
    launch_gemm(ym, mlp_w1 + (size_t)0, hbuf, L_IMG, D_MLP, D_MODEL, mlp_b1 + 0, 0, 0, 1);
    launch_gemm(hbuf, mlp_w2 + (size_t)0, out_img, L_IMG, D_MODEL, D_MLP,
                mlp_b2 + 0, mod + 0 * 6144 + 5120, x1 + off_img, 2);

    // 9. temporal MLP: LN of FINAL img (reference quirk)
    lnmod_kernel<<<L_TMP, 256>>>(out_img, ym, mod + 1 * 6144 + 3072, mod + 1 * 6144 + 4096);
    launch_gemm(ym, mlp_w1 + (size_t)1 * D_MODEL * D_MLP, hbuf, L_TMP, D_MLP, D_MODEL, mlp_b1 + D_MLP, 0, 0, 1);
    launch_gemm(hbuf, mlp_w2 + (size_t)1 * D_MLP * D_MODEL, out_tmp, L_TMP, D_MODEL, D_MLP,
                mlp_b2 + 1024, mod + 1 * 6144 + 5120, x1 + off_tmp, 2);

    // 10. txt MLP
    lnmod_kernel<<<L_TXT, 256>>>(x1 + off_txt, ym, mod + 2 * 6144 + 3072, mod + 2 * 6144 + 4096);
    launch_gemm(ym, mlp_w1 + (size_t)2 * D_MODEL * D_MLP, hbuf, L_TXT, D_MLP, D_MODEL, mlp_b1 + 2 * D_MLP, 0, 0, 1);
    launch_gemm(hbuf, mlp_w2 + (size_t)2 * D_MLP * D_MODEL, out_txt, L_TXT, D_MODEL, D_MLP,
                mlp_b2 + 2 * 1024, mod + 2 * 6144 + 5120, x1 + off_txt, 2);
}

// round 5
// speedup vs baseline: 4.8819x; 1.4229x over previous
#include <cuda_runtime.h>
#include <cuda_bf16.h>
#include <math.h>
#include <stdint.h>

// ---------------- problem constants ----------------
#define L_TXT 256
#define L_IMG 1024
#define L_TMP 1024
#define L_ALL 2304          // txt + img + tmp
#define D_MODEL 1024
#define NH 16
#define HD 64
#define D_MLP 4096
#define EPS 1e-6f
#define ATTN_SCALE 0.125f   // 1/sqrt(64)

// ---------------- scratch (static device memory; no allocation) ----------------
__device__ float g_sv[D_MODEL];
__device__ float g_mod[3 * 6144];
__device__ float g_res[L_ALL * D_MODEL];       // concat copy of original inputs [txt|img|tmp]
__device__ float g_xm[L_ALL * D_MODEL];        // LN1-modulated, concat order [txt|img|tmp]
__device__ float g_qkv[L_ALL * 3 * D_MODEL];   // QKV gemm out, same row order
__device__ float g_Q[NH * L_ALL * HD];
__device__ float g_K[NH * L_ALL * HD];
__device__ float g_V[NH * L_ALL * HD];
__device__ float g_attn[L_ALL * D_MODEL];      // [l][h*64+d], concat order
__device__ float g_x1[L_ALL * D_MODEL];        // post-proj residual, concat order
__device__ float g_ym[1280 * D_MODEL];         // LN2-modulated (img rows 0..1023, txt rows 1024..1279)
__device__ float g_h[1280 * D_MLP];            // MLP hidden

// ---------------- helpers ----------------
__device__ __forceinline__ float gelu_tanh(float x) {
    const float c = 0.7978845608028654f; // sqrt(2/pi)
    float x3 = x * x * x;
    return 0.5f * x * (1.f + tanhf(c * (x + 0.044715f * x3)));
}

__device__ __forceinline__ uint32_t f2tf32(float f) {
    uint32_t u;
    asm("cvt.rna.tf32.f32 %0, %1;" : "=r"(u) : "f"(f));
    return u;
}

__device__ __forceinline__ void mma_tf32(float& d0, float& d1, float& d2, float& d3,
                                         uint32_t a0, uint32_t a1, uint32_t a2, uint32_t a3,
                                         uint32_t b0, uint32_t b1) {
    asm volatile(
        "mma.sync.aligned.m16n8k8.row.col.f32.tf32.tf32.f32 "
        "{%0,%1,%2,%3}, {%4,%5,%6,%7}, {%8,%9}, {%0,%1,%2,%3};"
        : "+f"(d0), "+f"(d1), "+f"(d2), "+f"(d3)
        : "r"(a0), "r"(a1), "r"(a2), "r"(a3), "r"(b0), "r"(b1));
}

// ---------------- silu(vec) ----------------
__global__ void silu_kernel(const float* __restrict__ v, float* __restrict__ sv) {
    int t = threadIdx.x;
    float x = v[t];
    sv[t] = x / (1.f + expf(-x));
}

// ---------------- concat copy of residual sources ----------------
__global__ void copy3_kernel(const float* __restrict__ txt, const float* __restrict__ img,
                             const float* __restrict__ tmp, float* __restrict__ dst) {
    int i = blockIdx.x * 256 + threadIdx.x;    // float4 index, total L_ALL*1024/4
    const int ntxt = L_TXT * D_MODEL / 4;
    const int nimg = (L_TXT + L_IMG) * D_MODEL / 4;
    float4 v;
    if (i < ntxt)       v = ((const float4*)txt)[i];
    else if (i < nimg)  v = ((const float4*)img)[i - ntxt];
    else                v = ((const float4*)tmp)[i - nimg];
    ((float4*)dst)[i] = v;
}

// ---------------- mod = sv @ mod_w + mod_b  (3 x 6144 outputs) ----------------
__global__ void mod_kernel(const float* __restrict__ sv, const float* __restrict__ mod_w,
                           const float* __restrict__ mod_b, float* __restrict__ mod) {
    __shared__ float s_sv[D_MODEL];
    for (int i = threadIdx.x; i < D_MODEL; i += 256) s_sv[i] = sv[i];
    __syncthreads();
    int o = blockIdx.x * 256 + threadIdx.x;       // 0 .. 3*6144-1
    int i = o / 6144;
    int j = o - i * 6144;
    const float* w = mod_w + (size_t)i * D_MODEL * 6144 + j;
    float acc = 0.f;
    #pragma unroll 8
    for (int d = 0; d < D_MODEL; ++d) acc = fmaf(s_sv[d], w[(size_t)d * 6144], acc);
    mod[o] = acc + mod_b[o];
}

// ---------------- LN + modulate: out = (1+sc)*ln(x) + sh ----------------
__global__ void lnmod_kernel(const float* __restrict__ x, float* __restrict__ out,
                             const float* __restrict__ sh, const float* __restrict__ sc) {
    int r = blockIdx.x;
    const float* xr = x + (size_t)r * D_MODEL;
    int t = threadIdx.x; // 256
    float v[4]; float sum = 0.f, sq = 0.f;
    #pragma unroll
    for (int i = 0; i < 4; i++) { float f = xr[t + i * 256]; v[i] = f; sum += f; sq += f * f; }
    #pragma unroll
    for (int o = 16; o; o >>= 1) {
        sum += __shfl_xor_sync(0xffffffffu, sum, o);
        sq  += __shfl_xor_sync(0xffffffffu, sq, o);
    }
    __shared__ float ssum[8], ssq[8];
    int w = t >> 5, lane = t & 31;
    if (lane == 0) { ssum[w] = sum; ssq[w] = sq; }
    __syncthreads();
    if (t == 0) {
        float S = 0.f, Q = 0.f;
        #pragma unroll
        for (int i = 0; i < 8; i++) { S += ssum[i]; Q += ssq[i]; }
        float mean = S * (1.f / D_MODEL);
        float var  = Q * (1.f / D_MODEL) - mean * mean;
        ssum[0] = mean; ssq[0] = rsqrtf(var + EPS);
    }
    __syncthreads();
    float mean = ssum[0], inv = ssq[0];
    float* orow = out + (size_t)r * D_MODEL;
    #pragma unroll
    for (int i = 0; i < 4; i++) {
        int d = t + i * 256;
        orow[d] = (1.f + sc[d]) * ((v[i] - mean) * inv) + sh[d];
    }
}

// ---------------- tf32 tensor-core GEMM, fragment-packed smem, z-batched ----------------
// epi 0: C = acc;  epi 1: C = gelu(acc + bias);  epi 2: C = res + gate*(acc + bias)
#define TBM 128
#define TBN 128
#define TBK 16
// A fragment store: [oct][mblk(8)][lane(32)][4 words], padded per octet
#define A_OCT 1028          // 8*32*4 + 4
#define A_BUFW (2 * A_OCT)
// B fragment store: [oct][nblk(16) stride 66][lane*2 + slot]
#define B_NB 66
#define B_OCT 1058          // 16*66 + 2
#define B_BUFW (2 * B_OCT)

struct BArgs {
    int aoff[3];      // A row offset per z
    int coff[3];      // C row offset per z
    int roff[3];      // res row offset per z
    int m[3];         // rows per z
    long long woff[3];// weight element offset per z
    int boff[3];      // bias element offset per z
    int goff[3];      // gate element offset per z
};

__global__ void __launch_bounds__(256) gemm_tc_kernel(
        const float* __restrict__ A, const float* __restrict__ W,
        float* __restrict__ C, int N, int K,
        const float* __restrict__ bias,
        const float* __restrict__ gate,
        const float* __restrict__ res,
        int epi, BArgs ba) {
    int z = blockIdx.z;
    int brow = blockIdx.y, bcol = blockIdx.x;
    if (brow * TBM >= ba.m[z]) return;

    __shared__ uint32_t As[2][A_BUFW];
    __shared__ uint32_t Bs[2][B_BUFW];

    int tid  = threadIdx.x;
    int warp = tid >> 5;
    int lane = tid & 31;
    int gid  = lane >> 2;
    int tig  = lane & 3;
    int wm16 = (warp >> 2) * 4;     // mblk base (units of 16 rows)
    int wn8  = (warp & 3) * 4;      // nblk base (units of 8 cols)

    const float* Ab = A + (size_t)ba.aoff[z] * K;
    const float* Bb = W + ba.woff[z];

    // global load mapping
    int a_row = tid >> 1;              // 0..127
    int aoct  = tid & 1;               // octet 0/1 (k offset 0/8)
    int amblk = a_row >> 4;
    int ar8   = a_row & 7;
    int aslotb = (a_row & 8) ? 2 : 0;
    int b_row = tid >> 6;              // 0..3 (k rows b_row + r*4)
    int b_col = (tid & 63) * 2;        // 0..126

    const float* Aptr = Ab + (size_t)(brow * TBM + a_row) * K + aoct * 8;
    const float* Bptr = Bb + (size_t)b_row * N + bcol * TBN + b_col;

    float acc[4][4][4];
    #pragma unroll
    for (int i = 0; i < 4; i++)
        #pragma unroll
        for (int j = 0; j < 4; j++)
            #pragma unroll
            for (int c = 0; c < 4; c++) acc[i][j][c] = 0.f;

    int iters = K / TBK;

    float4 av0 = *(const float4*)(Aptr);
    float4 av1 = *(const float4*)(Aptr + 4);
    float2 bv[4];
    #pragma unroll
    for (int r = 0; r < 4; r++)
        bv[r] = *(const float2*)(Bptr + (size_t)(r * 4) * N);

    // --- store tile into fragment layout (raw f32 bits; HMMA truncates to tf32) ---
    #define STORE_TILE(BUF) do {                                                     \
        uint32_t* abase = &As[BUF][aoct * A_OCT + amblk * 128 + aslotb];             \
        ((float2*)(abase + (ar8 * 4 + 0) * 4))[0] = make_float2(av0.x, av1.x);       \
        ((float2*)(abase + (ar8 * 4 + 1) * 4))[0] = make_float2(av0.y, av1.y);       \
        ((float2*)(abase + (ar8 * 4 + 2) * 4))[0] = make_float2(av0.z, av1.z);       \
        ((float2*)(abase + (ar8 * 4 + 3) * 4))[0] = make_float2(av0.w, av1.w);       \
        _Pragma("unroll")                                                            \
        for (int r = 0; r < 4; r++) {                                                \
            int k   = b_row + r * 4;                                                 \
            int oct = k >> 3;                                                        \
            int j   = k & 7;                                                         \
            int jm  = j & 3;                                                         \
            int sl  = j >> 2;                                                        \
            int n7  = b_col & 7;                                                     \
            int nbl = b_col >> 3;                                                    \
            uint32_t* bb = &Bs[BUF][oct * B_OCT + nbl * B_NB + sl];                  \
            bb[(n7 * 4 + jm) * 2]       = __float_as_uint(bv[r].x);                  \
            bb[((n7 + 1) * 4 + jm) * 2] = __float_as_uint(bv[r].y);                  \
        }                                                                            \
    } while (0)

    STORE_TILE(0);
    __syncthreads();

    for (int it = 0; it < iters; ++it) {
        int cur = it & 1;
        if (it + 1 < iters) {
            int k0 = (it + 1) * TBK;
            av0 = *(const float4*)(Aptr + k0);
            av1 = *(const float4*)(Aptr + k0 + 4);
            #pragma unroll
            for (int r = 0; r < 4; r++)
                bv[r] = *(const float2*)(Bptr + (size_t)(k0 + r * 4) * N);
        }

        #pragma unroll
        for (int oct = 0; oct < 2; oct++) {
            uint4 ua[4];
            #pragma unroll
            for (int mt = 0; mt < 4; mt++)
                ua[mt] = *(const uint4*)&As[cur][oct * A_OCT + (wm16 + mt) * 128 + lane * 4];
            uint2 ub[4];
            #pragma unroll
            for (int nt = 0; nt < 4; nt++)
                ub[nt] = *(const uint2*)&Bs[cur][oct * B_OCT + (wn8 + nt) * B_NB + lane * 2];
            #pragma unroll
            for (int mt = 0; mt < 4; mt++)
                #pragma unroll
                for (int nt = 0; nt < 4; nt++)
                    mma_tf32(acc[mt][nt][0], acc[mt][nt][1], acc[mt][nt][2], acc[mt][nt][3],
                             ua[mt].x, ua[mt].z, ua[mt].y, ua[mt].w,
                             ub[nt].x, ub[nt].y);
        }

        if (it + 1 < iters) {
            int nxt = cur ^ 1;
            STORE_TILE(nxt);
            __syncthreads();
        }
    }
    #undef STORE_TILE

    // epilogue
    int wm = (warp >> 2) * 64;
    int wn = (warp & 3) * 32;
    int crow = ba.coff[z];
    int rrow = ba.roff[z];
    int bo = ba.boff[z], go = ba.goff[z];
    #pragma unroll
    for (int mt = 0; mt < 4; mt++) {
        int lrow0 = brow * TBM + wm + mt * 16 + gid;
        int lrow1 = lrow0 + 8;
        #pragma unroll
        for (int nt = 0; nt < 4; nt++) {
            int col0 = bcol * TBN + wn + nt * 8 + tig * 2;
            int col1 = col0 + 1;
            float v0 = acc[mt][nt][0], v1 = acc[mt][nt][1];
            float v2 = acc[mt][nt][2], v3 = acc[mt][nt][3];
            if (epi == 1) {
                v0 = gelu_tanh(v0 + bias[bo + col0]); v1 = gelu_tanh(v1 + bias[bo + col1]);
                v2 = gelu_tanh(v2 + bias[bo + col0]); v3 = gelu_tanh(v3 + bias[bo + col1]);
            } else if (epi == 2) {
                v0 = res[(size_t)(rrow + lrow0) * N + col0] + gate[go + col0] * (v0 + bias[bo + col0]);
                v1 = res[(size_t)(rrow + lrow0) * N + col1] + gate[go + col1] * (v1 + bias[bo + col1]);
                v2 = res[(size_t)(rrow + lrow1) * N + col0] + gate[go + col0] * (v2 + bias[bo + col0]);
                v3 = res[(size_t)(rrow + lrow1) * N + col1] + gate[go + col1] * (v3 + bias[bo + col1]);
            }
            C[(size_t)(crow + lrow0) * N + col0] = v0;
            C[(size_t)(crow + lrow0) * N + col1] = v1;
            C[(size_t)(crow + lrow1) * N + col0] = v2;
            C[(size_t)(crow + lrow1) * N + col1] = v3;
        }
    }
}

// ---------------- QKV post: RMS + scale + RoPE + scatter to head-major ----------------
__global__ void qkvpost_kernel(const float* __restrict__ Y, const float* __restrict__ pe,
                               const float* __restrict__ q_scale, const float* __restrict__ k_scale,
                               float* __restrict__ Q, float* __restrict__ K, float* __restrict__ V) {
    int gw = blockIdx.x * 8 + (threadIdx.x >> 5);   // warp id: 0 .. 2304*16-1
    int lane = threadIdx.x & 31;
    int l = gw >> 4;
    int h = gw & 15;
    int i = (l < L_TXT) ? 2 : (l < (L_TXT + L_IMG) ? 0 : 1);
    bool is_tmp = (l >= L_TXT + L_IMG);

    const float* row = Y + (size_t)l * 3072 + h * HD;
    float q0 = row[2 * lane],        q1 = row[2 * lane + 1];
    float k0 = row[1024 + 2 * lane], k1 = row[1024 + 2 * lane + 1];
    float v0 = row[2048 + 2 * lane], v1 = row[2048 + 2 * lane + 1];

    float qs = q0 * q0 + q1 * q1;
    float ks = k0 * k0 + k1 * k1;
    #pragma unroll
    for (int o = 16; o; o >>= 1) {
        qs += __shfl_xor_sync(0xffffffffu, qs, o);
        ks += __shfl_xor_sync(0xffffffffu, ks, o);
    }
    float qinv = rsqrtf(qs * (1.f / HD) + EPS);
    float kinv = rsqrtf(ks * (1.f / HD) + EPS);

    float qn0 = q0 * qinv * q_scale[i * HD + 2 * lane];
    float qn1 = q1 * qinv * q_scale[i * HD + 2 * lane + 1];
    float kn0 = k0 * kinv * k_scale[i * HD + 2 * lane];
    float kn1 = k1 * kinv * k_scale[i * HD + 2 * lane + 1];

    const float* p = pe + ((size_t)l * 32 + lane) * 4;
    float p00 = p[0], p01 = p[1], p10 = p[2], p11 = p[3];

    size_t base = ((size_t)h * L_ALL + l) * HD + 2 * lane;
    Q[base]     = p00 * qn0 + p01 * qn1;
    Q[base + 1] = p10 * qn0 + p11 * qn1;
    K[base]     = p00 * kn0 + p01 * kn1;
    K[base + 1] = p10 * kn0 + p11 * kn1;
    if (is_tmp) { V[base] = qn0; V[base + 1] = qn1; }
    else        { V[base] = v0;  V[base + 1] = v1;  }
}

// ---------------- flash attention on tensor cores (tf32 mma) ----------------
#define ATQ 64
#define ATK 64
#define ALD 68

__global__ void __launch_bounds__(128) attn_tc_kernel(
        const float* __restrict__ Q, const float* __restrict__ K,
        const float* __restrict__ V, float* __restrict__ Aout) {
    extern __shared__ uint32_t dyn[];
    uint32_t (*Ks)[ALD] = (uint32_t(*)[ALD])dyn;
    uint32_t (*Vs)[ALD] = (uint32_t(*)[ALD])(dyn + ATK * ALD);
    uint32_t (*Ps)[ALD] = (uint32_t(*)[ALD])(dyn + 2 * ATK * ALD);

    int h   = blockIdx.y;
    int q0  = blockIdx.x * ATQ;
    int tid = threadIdx.x;          // 128
    int warp = tid >> 5;
    int lane = tid & 31;
    int gid  = lane >> 2;
    int tig  = lane & 3;
    int w16  = warp * 16;

    const float* Qh = Q + (size_t)h * L_ALL * HD;
    const float* Kh = K + (size_t)h * L_ALL * HD;
    const float* Vh = V + (size_t)h * L_ALL * HD;

    #pragma unroll
    for (int i = 0; i < 8; i++) {
        int linear = tid + i * 128;
        int r = linear >> 4;
        int c4 = (linear & 15) * 4;
        float4 qv = *(const float4*)(Qh + (size_t)(q0 + r) * HD + c4);
        Ps[r][c4 + 0] = f2tf32(qv.x * ATTN_SCALE);
        Ps[r][c4 + 1] = f2tf32(qv.y * ATTN_SCALE);
        Ps[r][c4 + 2] = f2tf32(qv.z * ATTN_SCALE);
        Ps[r][c4 + 3] = f2tf32(qv.w * ATTN_SCALE);
    }
    __syncthreads();

    uint32_t qf[8][4];
    #pragma unroll
    for (int ks = 0; ks < 8; ks++) {
        qf[ks][0] = Ps[w16 + gid][ks * 8 + tig];
        qf[ks][1] = Ps[w16 + gid + 8][ks * 8 + tig];
        qf[ks][2] = Ps[w16 + gid][ks * 8 + tig + 4];
        qf[ks][3] = Ps[w16 + gid + 8][ks * 8 + tig + 4];
    }

    float oacc[8][4];
    #pragma unroll
    for (int nt = 0; nt < 8; nt++)
        #pragma unroll
        for (int c = 0; c < 4; c++) oacc[nt][c] = 0.f;
    float m0 = -INFINITY, m1 = -INFINITY, l0 = 0.f, l1 = 0.f;

    for (int kb = 0; kb < L_ALL; kb += ATK) {
        __syncthreads();
        #pragma unroll
        for (int i = 0; i < 8; i++) {
            int linear = tid + i * 128;
            int r = linear >> 4;
            int c4 = (linear & 15) * 4;
            float4 kv = *(const float4*)(Kh + (size_t)(kb + r) * HD + c4);
            float4 vv = *(const float4*)(Vh + (size_t)(kb + r) * HD + c4);
            Ks[r][c4 + 0] = f2tf32(kv.x); Ks[r][c4 + 1] = f2tf32(kv.y);
            Ks[r][c4 + 2] = f2tf32(kv.z); Ks[r][c4 + 3] = f2tf32(kv.w);
            Vs[r][c4 + 0] = f2tf32(vv.x); Vs[r][c4 + 1] = f2tf32(vv.y);
            Vs[r][c4 + 2] = f2tf32(vv.z); Vs[r][c4 + 3] = f2tf32(vv.w);
        }
        __syncthreads();

        float sacc[8][4];
        #pragma unroll
        for (int nt = 0; nt < 8; nt++)
            #pragma unroll
            for (int c = 0; c < 4; c++) sacc[nt][c] = 0.f;
        #pragma unroll
        for (int ks = 0; ks < 8; ks++) {
            #pragma unroll
            for (int nt = 0; nt < 8; nt++) {
                uint32_t b0 = Ks[nt * 8 + gid][ks * 8 + tig];
                uint32_t b1 = Ks[nt * 8 + gid][ks * 8 + tig + 4];
                mma_tf32(sacc[nt][0], sacc[nt][1], sacc[nt][2], sacc[nt][3],
                         qf[ks][0], qf[ks][1], qf[ks][2], qf[ks][3], b0, b1);
            }
        }

        float t0 = -INFINITY, t1 = -INFINITY;
        #pragma unroll
        for (int nt = 0; nt < 8; nt++) {
            t0 = fmaxf(t0, fmaxf(sacc[nt][0], sacc[nt][1]));
            t1 = fmaxf(t1, fmaxf(sacc[nt][2], sacc[nt][3]));
        }
        t0 = fmaxf(t0, __shfl_xor_sync(0xffffffffu, t0, 1));
        t0 = fmaxf(t0, __shfl_xor_sync(0xffffffffu, t0, 2));
        t1 = fmaxf(t1, __shfl_xor_sync(0xffffffffu, t1, 1));
        t1 = fmaxf(t1, __shfl_xor_sync(0xffffffffu, t1, 2));
        float mn0 = fmaxf(m0, t0), mn1 = fmaxf(m1, t1);
        float al0 = __expf(m0 - mn0), al1 = __expf(m1 - mn1);
        m0 = mn0; m1 = mn1;

        float ts0 = 0.f, ts1 = 0.f;
        #pragma unroll
        for (int nt = 0; nt < 8; nt++) {
            int c0 = nt * 8 + tig * 2;
            uint32_t p00 = f2tf32(__expf(sacc[nt][0] - mn0));
            uint32_t p01 = f2tf32(__expf(sacc[nt][1] - mn0));
            uint32_t p10 = f2tf32(__expf(sacc[nt][2] - mn1));
            uint32_t p11 = f2tf32(__expf(sacc[nt][3] - mn1));
            Ps[w16 + gid][c0]         = p00;
            Ps[w16 + gid][c0 + 1]     = p01;
            Ps[w16 + gid + 8][c0]     = p10;
            Ps[w16 + gid + 8][c0 + 1] = p11;
            ts0 += __uint_as_float(p00) + __uint_as_float(p01);
            ts1 += __uint_as_float(p10) + __uint_as_float(p11);
        }
        ts0 += __shfl_xor_sync(0xffffffffu, ts0, 1);
        ts0 += __shfl_xor_sync(0xffffffffu, ts0, 2);
        ts1 += __shfl_xor_sync(0xffffffffu, ts1, 1);
        ts1 += __shfl_xor_sync(0xffffffffu, ts1, 2);
        l0 = l0 * al0 + ts0;
        l1 = l1 * al1 + ts1;

        #pragma unroll
        for (int nt = 0; nt < 8; nt++) {
            oacc[nt][0] *= al0; oacc[nt][1] *= al0;
            oacc[nt][2] *= al1; oacc[nt][3] *= al1;
        }
        __syncwarp();

        #pragma unroll
        for (int ks = 0; ks < 8; ks++) {
            uint32_t a0 = Ps[w16 + gid][ks * 8 + tig];
            uint32_t a1 = Ps[w16 + gid + 8][ks * 8 + tig];
            uint32_t a2 = Ps[w16 + gid][ks * 8 + tig + 4];
            uint32_t a3 = Ps[w16 + gid + 8][ks * 8 + tig + 4];
            #pragma unroll
            for (int nt = 0; nt < 8; nt++) {
                uint32_t b0 = Vs[ks * 8 + tig][nt * 8 + gid];
                uint32_t b1 = Vs[ks * 8 + tig + 4][nt * 8 + gid];
                mma_tf32(oacc[nt][0], oacc[nt][1], oacc[nt][2], oacc[nt][3],
                         a0, a1, a2, a3, b0, b1);
            }
        }
        __syncwarp();
    }

    float i0 = 1.f / l0, i1 = 1.f / l1;
    int r0 = q0 + w16 + gid;
    int r1 = r0 + 8;
    #pragma unroll
    for (int nt = 0; nt < 8; nt++) {
        int c0 = h * HD + nt * 8 + tig * 2;
        Aout[(size_t)r0 * D_MODEL + c0]     = oacc[nt][0] * i0;
        Aout[(size_t)r0 * D_MODEL + c0 + 1] = oacc[nt][1] * i0;
        Aout[(size_t)r1 * D_MODEL + c0]     = oacc[nt][2] * i1;
        Aout[(size_t)r1 * D_MODEL + c0 + 1] = oacc[nt][3] * i1;
    }
}

#define ATTN_SMEM (3 * ATK * ALD * 4)

extern "C" void kernel_launch(void* const* d_in, const int* in_sizes, int n_in,
                              void* d_out, int out_size) {
    const float* img      = (const float*)d_in[0];
    const float* temporal = (const float*)d_in[1];
    const float* txt      = (const float*)d_in[2];
    const float* vec      = (const float*)d_in[3];
    const float* pe       = (const float*)d_in[4];
    const float* mod_w    = (const float*)d_in[5];
    const float* mod_b    = (const float*)d_in[6];
    const float* qkv_w    = (const float*)d_in[7];
    const float* q_scale  = (const float*)d_in[8];
    const float* k_scale  = (const float*)d_in[9];
    const float* proj_w   = (const float*)d_in[10];
    const float* proj_b   = (const float*)d_in[11];
    const float* mlp_w1   = (const float*)d_in[12];
    const float* mlp_b1   = (const float*)d_in[13];
    const float* mlp_w2   = (const float*)d_in[14];
    const float* mlp_b2   = (const float*)d_in[15];
    float* out = (float*)d_out;

    static float *sv = 0, *mod = 0, *res = 0, *xm = 0, *qkv = 0, *Qb = 0, *Kb = 0, *Vb = 0,
                 *attn = 0, *x1 = 0, *ym = 0, *hbuf = 0;
    if (!sv) {
        cudaGetSymbolAddress((void**)&sv,   g_sv);
        cudaGetSymbolAddress((void**)&mod,  g_mod);
        cudaGetSymbolAddress((void**)&res,  g_res);
        cudaGetSymbolAddress((void**)&xm,   g_xm);
        cudaGetSymbolAddress((void**)&qkv,  g_qkv);
        cudaGetSymbolAddress((void**)&Qb,   g_Q);
        cudaGetSymbolAddress((void**)&Kb,   g_K);
        cudaGetSymbolAddress((void**)&Vb,   g_V);
        cudaGetSymbolAddress((void**)&attn, g_attn);
        cudaGetSymbolAddress((void**)&x1,   g_x1);
        cudaGetSymbolAddress((void**)&ym,   g_ym);
        cudaGetSymbolAddress((void**)&hbuf, g_h);
        cudaFuncSetAttribute(attn_tc_kernel,
                             cudaFuncAttributeMaxDynamicSharedMemorySize, ATTN_SMEM);
    }

    const int off_txt = 0;
    const int off_img = L_TXT;
    const int off_tmp = L_TXT + L_IMG;

    // 1. independent prep
    silu_kernel<<<1, 1024>>>(vec, sv);
    copy3_kernel<<<(L_ALL * D_MODEL / 4) / 256, 256>>>(txt, img, temporal, res);
    mod_kernel<<<(3 * 6144) / 256, 256>>>(sv, mod_w, mod_b, mod);

    // 2. LN1 + modulate
    lnmod_kernel<<<L_TXT, 256>>>(txt,      xm + (size_t)off_txt * D_MODEL, mod + 2 * 6144, mod + 2 * 6144 + 1024);
    lnmod_kernel<<<L_IMG, 256>>>(img,      xm + (size_t)off_img * D_MODEL, mod + 0,        mod + 1024);
    lnmod_kernel<<<L_TMP, 256>>>(temporal, xm + (size_t)off_tmp * D_MODEL, mod + 1 * 6144, mod + 1 * 6144 + 1024);

    // 3. QKV (batched z=3: txt->w2, img->w0, tmp->w1)
    {
        BArgs ba = {};
        int ao[3] = {off_txt, off_img, off_tmp};
        for (int z = 0; z < 3; z++) { ba.aoff[z] = ao[z]; ba.coff[z] = ao[z]; }
        ba.m[0] = 256; ba.m[1] = 1024; ba.m[2] = 1024;
        ba.woff[0] = 2LL * 1024 * 3072; ba.woff[1] = 0; ba.woff[2] = 1LL * 1024 * 3072;
        gemm_tc_kernel<<<dim3(3072 / TBN, 8, 3), 256>>>(xm, qkv_w, qkv, 3072, 1024,
                                                        proj_b, mod, res, 0, ba);
    }

    // 4. RMS + scale + RoPE + scatter
    qkvpost_kernel<<<(L_ALL * NH) / 8, 256>>>(qkv, pe, q_scale, k_scale, Qb, Kb, Vb);

    // 5. attention
    attn_tc_kernel<<<dim3(L_ALL / ATQ, NH), 128, ATTN_SMEM>>>(Qb, Kb, Vb, attn);

    // 6. proj + gate + residual (batched z=3)
    {
        BArgs ba = {};
        int ao[3] = {off_txt, off_img, off_tmp};
        int wi[3] = {2, 0, 1};
        for (int z = 0; z < 3; z++) {
            ba.aoff[z] = ao[z]; ba.coff[z] = ao[z]; ba.roff[z] = ao[z];
            ba.woff[z] = (long long)wi[z] * 1024 * 1024;
            ba.boff[z] = wi[z] * 1024;
            ba.goff[z] = wi[z] * 6144 + 2048;
        }
        ba.m[0] = 256; ba.m[1] = 1024; ba.m[2] = 1024;
        gemm_tc_kernel<<<dim3(1024 / TBN, 8, 3), 256>>>(attn, proj_w, x1, 1024, 1024,
                                                        proj_b, mod, res, 2, ba);
    }

    // 7. img + txt MLP (batched z=2); temporal must wait for final img
    lnmod_kernel<<<L_IMG, 256>>>(x1 + (size_t)off_img * D_MODEL, ym,
                                 mod + 0 * 6144 + 3072, mod + 0 * 6144 + 4096);
    lnmod_kernel<<<L_TXT, 256>>>(x1 + (size_t)off_txt * D_MODEL, ym + (size_t)1024 * D_MODEL,
                                 mod + 2 * 6144 + 3072, mod + 2 * 6144 + 4096);
    {
        BArgs ba = {};
        ba.aoff[0] = 0;    ba.coff[0] = 0;    ba.m[0] = 1024;
        ba.woff[0] = 0;    ba.boff[0] = 0;
        ba.aoff[1] = 1024; ba.coff[1] = 1024; ba.m[1] = 256;
        ba.woff[1] = 2LL * 1024 * 4096; ba.boff[1] = 2 * 4096;
        gemm_tc_kernel<<<dim3(4096 / TBN, 8, 2), 256>>>(ym, mlp_w1, hbuf, 4096, 1024,
                                                        mlp_b1, mod, res, 1, ba);
    }
    {
        BArgs ba = {};
        // z0: img -> out rows [0,1024), res = x1 img rows
        ba.aoff[0] = 0;    ba.coff[0] = 0;    ba.roff[0] = off_img; ba.m[0] = 1024;
        ba.woff[0] = 0;    ba.boff[0] = 0;    ba.goff[0] = 0 * 6144 + 5120;
        // z1: txt -> out rows [2048,2304), res = x1 txt rows
        ba.aoff[1] = 1024; ba.coff[1] = 2048; ba.roff[1] = off_txt; ba.m[1] = 256;
        ba.woff[1] = 2LL * 4096 * 1024; ba.boff[1] = 2 * 1024; ba.goff[1] = 2 * 6144 + 5120;
        gemm_tc_kernel<<<dim3(1024 / TBN, 8, 2), 256>>>(hbuf, mlp_w2, out, 1024, 4096,
                                                        mlp_b2, mod, x1, 2, ba);
    }

    // 8. temporal MLP: LN of FINAL img (reference quirk), residual = x1 tmp rows
    lnmod_kernel<<<L_TMP, 256>>>(out, ym, mod + 1 * 6144 + 3072, mod + 1 * 6144 + 4096);
    {
        BArgs ba = {};
        ba.aoff[0] = 0; ba.coff[0] = 0; ba.m[0] = 1024;
        ba.woff[0] = 1LL * 1024 * 4096; ba.boff[0] = 4096;
        gemm_tc_kernel<<<dim3(4096 / TBN, 8, 1), 256>>>(ym, mlp_w1, hbuf, 4096, 1024,
                                                        mlp_b1, mod, res, 1, ba);
    }
    {
        BArgs ba = {};
        ba.aoff[0] = 0; ba.coff[0] = 1024; ba.roff[0] = off_tmp; ba.m[0] = 1024;
        ba.woff[0] = 1LL * 4096 * 1024; ba.boff[0] = 1024; ba.goff[0] = 1 * 6144 + 5120;
        gemm_tc_kernel<<<dim3(1024 / TBN, 8, 1), 256>>>(hbuf, mlp_w2, out, 1024, 4096,
                                                        mlp_b2, mod, x1, 2, ba);
    }
}

// round 6
// speedup vs baseline: 5.0115x; 1.0265x over previous
#include <cuda_runtime.h>
#include <cuda_bf16.h>
#include <math.h>
#include <stdint.h>

// ---------------- problem constants ----------------
#define L_TXT 256
#define L_IMG 1024
#define L_TMP 1024
#define L_ALL 2304          // txt + img + tmp
#define D_MODEL 1024
#define NH 16
#define HD 64
#define D_MLP 4096
#define EPS 1e-6f
#define ATTN_SCALE 0.125f   // 1/sqrt(64)

// ---------------- scratch (static device memory; no allocation) ----------------
__device__ float g_sv[D_MODEL];
__device__ float g_mod[3 * 6144];
__device__ float g_res[L_ALL * D_MODEL];       // concat copy of original inputs [txt|img|tmp]
__device__ float g_xm[L_ALL * D_MODEL];        // LN1-modulated, concat order [txt|img|tmp]
__device__ float g_qkv[L_ALL * 3 * D_MODEL];   // QKV gemm out, same row order
__device__ float g_Q[NH * L_ALL * HD];
__device__ float g_K[NH * L_ALL * HD];
__device__ float g_V[NH * L_ALL * HD];
__device__ float g_attn[L_ALL * D_MODEL];      // [l][h*64+d], concat order
__device__ float g_x1[L_ALL * D_MODEL];        // post-proj residual, concat order
__device__ float g_ym[1280 * D_MODEL];         // LN2-modulated (img rows 0..1023, txt rows 1024..1279)
__device__ float g_h[1280 * D_MLP];            // MLP hidden

// ---------------- helpers ----------------
__device__ __forceinline__ float gelu_tanh(float x) {
    const float c = 0.7978845608028654f; // sqrt(2/pi)
    float x3 = x * x * x;
    return 0.5f * x * (1.f + tanhf(c * (x + 0.044715f * x3)));
}

__device__ __forceinline__ uint32_t f2tf32(float f) {
    uint32_t u;
    asm("cvt.rna.tf32.f32 %0, %1;" : "=r"(u) : "f"(f));
    return u;
}

__device__ __forceinline__ void mma_tf32(float& d0, float& d1, float& d2, float& d3,
                                         uint32_t a0, uint32_t a1, uint32_t a2, uint32_t a3,
                                         uint32_t b0, uint32_t b1) {
    asm volatile(
        "mma.sync.aligned.m16n8k8.row.col.f32.tf32.tf32.f32 "
        "{%0,%1,%2,%3}, {%4,%5,%6,%7}, {%8,%9}, {%0,%1,%2,%3};"
        : "+f"(d0), "+f"(d1), "+f"(d2), "+f"(d3)
        : "r"(a0), "r"(a1), "r"(a2), "r"(a3), "r"(b0), "r"(b1));
}

// ---------------- silu(vec) ----------------
__global__ void silu_kernel(const float* __restrict__ v, float* __restrict__ sv) {
    int t = threadIdx.x;
    float x = v[t];
    sv[t] = x / (1.f + expf(-x));
}

// ---------------- concat copy of residual sources ----------------
__global__ void copy3_kernel(const float* __restrict__ txt, const float* __restrict__ img,
                             const float* __restrict__ tmp, float* __restrict__ dst) {
    int i = blockIdx.x * 256 + threadIdx.x;    // float4 index, total L_ALL*1024/4
    const int ntxt = L_TXT * D_MODEL / 4;
    const int nimg = (L_TXT + L_IMG) * D_MODEL / 4;
    float4 v;
    if (i < ntxt)       v = ((const float4*)txt)[i];
    else if (i < nimg)  v = ((const float4*)img)[i - ntxt];
    else                v = ((const float4*)tmp)[i - nimg];
    ((float4*)dst)[i] = v;
}

// ---------------- mod = sv @ mod_w + mod_b  (3 x 6144 outputs) ----------------
__global__ void mod_kernel(const float* __restrict__ sv, const float* __restrict__ mod_w,
                           const float* __restrict__ mod_b, float* __restrict__ mod) {
    __shared__ float s_sv[D_MODEL];
    for (int i = threadIdx.x; i < D_MODEL; i += 256) s_sv[i] = sv[i];
    __syncthreads();
    int o = blockIdx.x * 256 + threadIdx.x;       // 0 .. 3*6144-1
    int i = o / 6144;
    int j = o - i * 6144;
    const float* w = mod_w + (size_t)i * D_MODEL * 6144 + j;
    float acc = 0.f;
    #pragma unroll 8
    for (int d = 0; d < D_MODEL; ++d) acc = fmaf(s_sv[d], w[(size_t)d * 6144], acc);
    mod[o] = acc + mod_b[o];
}

// ---------------- LN + modulate: out = (1+sc)*ln(x) + sh ----------------
__global__ void lnmod_kernel(const float* __restrict__ x, float* __restrict__ out,
                             const float* __restrict__ sh, const float* __restrict__ sc) {
    int r = blockIdx.x;
    const float* xr = x + (size_t)r * D_MODEL;
    int t = threadIdx.x; // 256
    float v[4]; float sum = 0.f, sq = 0.f;
    #pragma unroll
    for (int i = 0; i < 4; i++) { float f = xr[t + i * 256]; v[i] = f; sum += f; sq += f * f; }
    #pragma unroll
    for (int o = 16; o; o >>= 1) {
        sum += __shfl_xor_sync(0xffffffffu, sum, o);
        sq  += __shfl_xor_sync(0xffffffffu, sq, o);
    }
    __shared__ float ssum[8], ssq[8];
    int w = t >> 5, lane = t & 31;
    if (lane == 0) { ssum[w] = sum; ssq[w] = sq; }
    __syncthreads();
    if (t == 0) {
        float S = 0.f, Q = 0.f;
        #pragma unroll
        for (int i = 0; i < 8; i++) { S += ssum[i]; Q += ssq[i]; }
        float mean = S * (1.f / D_MODEL);
        float var  = Q * (1.f / D_MODEL) - mean * mean;
        ssum[0] = mean; ssq[0] = rsqrtf(var + EPS);
    }
    __syncthreads();
    float mean = ssum[0], inv = ssq[0];
    float* orow = out + (size_t)r * D_MODEL;
    #pragma unroll
    for (int i = 0; i < 4; i++) {
        int d = t + i * 256;
        orow[d] = (1.f + sc[d]) * ((v[i] - mean) * inv) + sh[d];
    }
}

// ---------------- tf32 tensor-core GEMM, 64x128 tiles, fragment-packed, z-batched ----------------
// epi 0: C = acc;  epi 1: C = gelu(acc + bias);  epi 2: C = res + gate*(acc + bias)
#define TBM 64
#define TBN 128
#define TBK 16
// A fragment store: [oct(2)][mblk(4)][lane(32)][4 words] + pad
#define A_OCT 516           // 4*32*4 + 4
#define A_BUFW (2 * A_OCT)
// B fragment store: [oct(2)][nblk(16) stride 66][lane*2 + slot]
#define B_NB 66
#define B_OCT 1058          // 16*66 + 2
#define B_BUFW (2 * B_OCT)

struct BArgs {
    int aoff[3];      // A row offset per z
    int coff[3];      // C row offset per z
    int roff[3];      // res row offset per z
    int m[3];         // rows per z
    long long woff[3];// weight element offset per z
    int boff[3];      // bias element offset per z
    int goff[3];      // gate element offset per z
};

__global__ void __launch_bounds__(256) gemm_tc_kernel(
        const float* __restrict__ A, const float* __restrict__ W,
        float* __restrict__ C, int N, int K,
        const float* __restrict__ bias,
        const float* __restrict__ gate,
        const float* __restrict__ res,
        int epi, BArgs ba) {
    int z = blockIdx.z;
    int brow = blockIdx.y, bcol = blockIdx.x;
    if (brow * TBM >= ba.m[z]) return;

    __shared__ uint32_t As[2][A_BUFW];
    __shared__ uint32_t Bs[2][B_BUFW];

    int tid  = threadIdx.x;
    int warp = tid >> 5;
    int lane = tid & 31;
    int gid  = lane >> 2;
    int tig  = lane & 3;
    int wm2  = (warp >> 2) * 2;     // mblk base (0 or 2)
    int wn8  = (warp & 3) * 4;      // nblk base

    const float* Ab = A + (size_t)ba.aoff[z] * K;
    const float* Bb = W + ba.woff[z];

    // global load mapping
    int a_row = tid >> 2;              // 0..63
    int a_k4  = (tid & 3) * 4;         // 0,4,8,12
    int aoct  = a_k4 >> 3;
    int asl   = (a_k4 >> 2) & 1;
    int abase = aoct * A_OCT + (a_row >> 4) * 128 + (a_row & 7) * 16
              + ((a_row >> 3) & 1) * 2 + asl;

    int b_row = tid >> 6;              // 0..3 (k rows b_row + r*4)
    int b_col = (tid & 63) * 2;        // 0..126

    const float* Aptr = Ab + (size_t)(brow * TBM + a_row) * K + a_k4;
    const float* Bptr = Bb + (size_t)b_row * N + bcol * TBN + b_col;

    float acc[2][4][4];
    #pragma unroll
    for (int i = 0; i < 2; i++)
        #pragma unroll
        for (int j = 0; j < 4; j++)
            #pragma unroll
            for (int c = 0; c < 4; c++) acc[i][j][c] = 0.f;

    int iters = K / TBK;

    float4 av = *(const float4*)(Aptr);
    float2 bv[4];
    #pragma unroll
    for (int r = 0; r < 4; r++)
        bv[r] = *(const float2*)(Bptr + (size_t)(r * 4) * N);

    // store tile into fragment layout (raw f32 bits; HMMA truncates to tf32)
    #define STORE_TILE(BUF) do {                                                     \
        As[BUF][abase + 0]  = __float_as_uint(av.x);                                 \
        As[BUF][abase + 4]  = __float_as_uint(av.y);                                 \
        As[BUF][abase + 8]  = __float_as_uint(av.z);                                 \
        As[BUF][abase + 12] = __float_as_uint(av.w);                                 \
        _Pragma("unroll")                                                            \
        for (int r = 0; r < 4; r++) {                                                \
            int k   = b_row + r * 4;                                                 \
            int oct = k >> 3;                                                        \
            int j   = k & 7;                                                         \
            int jm  = j & 3;                                                         \
            int sl  = j >> 2;                                                        \
            int n7  = b_col & 7;                                                     \
            int nbl = b_col >> 3;                                                    \
            uint32_t* bb = &Bs[BUF][oct * B_OCT + nbl * B_NB + sl];                  \
            bb[(n7 * 4 + jm) * 2]       = __float_as_uint(bv[r].x);                  \
            bb[((n7 + 1) * 4 + jm) * 2] = __float_as_uint(bv[r].y);                  \
        }                                                                            \
    } while (0)

    STORE_TILE(0);
    __syncthreads();

    for (int it = 0; it < iters; ++it) {
        int cur = it & 1;
        if (it + 1 < iters) {
            int k0 = (it + 1) * TBK;
            av = *(const float4*)(Aptr + k0);
            #pragma unroll
            for (int r = 0; r < 4; r++)
                bv[r] = *(const float2*)(Bptr + (size_t)(k0 + r * 4) * N);
        }

        #pragma unroll
        for (int oct = 0; oct < 2; oct++) {
            uint4 ua[2];
            #pragma unroll
            for (int mt = 0; mt < 2; mt++)
                ua[mt] = *(const uint4*)&As[cur][oct * A_OCT + (wm2 + mt) * 128 + lane * 4];
            uint2 ub[4];
            #pragma unroll
            for (int nt = 0; nt < 4; nt++)
                ub[nt] = *(const uint2*)&Bs[cur][oct * B_OCT + (wn8 + nt) * B_NB + lane * 2];
            #pragma unroll
            for (int mt = 0; mt < 2; mt++)
                #pragma unroll
                for (int nt = 0; nt < 4; nt++)
                    mma_tf32(acc[mt][nt][0], acc[mt][nt][1], acc[mt][nt][2], acc[mt][nt][3],
                             ua[mt].x, ua[mt].z, ua[mt].y, ua[mt].w,
                             ub[nt].x, ub[nt].y);
        }

        if (it + 1 < iters) {
            int nxt = cur ^ 1;
            STORE_TILE(nxt);
            __syncthreads();
        }
    }
    #undef STORE_TILE

    // epilogue
    int wm = (warp >> 2) * 32;
    int wn = (warp & 3) * 32;
    int crow = ba.coff[z];
    int rrow = ba.roff[z];
    int bo = ba.boff[z], go = ba.goff[z];
    #pragma unroll
    for (int mt = 0; mt < 2; mt++) {
        int lrow0 = brow * TBM + wm + mt * 16 + gid;
        int lrow1 = lrow0 + 8;
        #pragma unroll
        for (int nt = 0; nt < 4; nt++) {
            int col0 = bcol * TBN + wn + nt * 8 + tig * 2;
            int col1 = col0 + 1;
            float v0 = acc[mt][nt][0], v1 = acc[mt][nt][1];
            float v2 = acc[mt][nt][2], v3 = acc[mt][nt][3];
            if (epi == 1) {
                v0 = gelu_tanh(v0 + bias[bo + col0]); v1 = gelu_tanh(v1 + bias[bo + col1]);
                v2 = gelu_tanh(v2 + bias[bo + col0]); v3 = gelu_tanh(v3 + bias[bo + col1]);
            } else if (epi == 2) {
                v0 = res[(size_t)(rrow + lrow0) * N + col0] + gate[go + col0] * (v0 + bias[bo + col0]);
                v1 = res[(size_t)(rrow + lrow0) * N + col1] + gate[go + col1] * (v1 + bias[bo + col1]);
                v2 = res[(size_t)(rrow + lrow1) * N + col0] + gate[go + col0] * (v2 + bias[bo + col0]);
                v3 = res[(size_t)(rrow + lrow1) * N + col1] + gate[go + col1] * (v3 + bias[bo + col1]);
            }
            C[(size_t)(crow + lrow0) * N + col0] = v0;
            C[(size_t)(crow + lrow0) * N + col1] = v1;
            C[(size_t)(crow + lrow1) * N + col0] = v2;
            C[(size_t)(crow + lrow1) * N + col1] = v3;
        }
    }
}

// ---------------- QKV post: RMS + scale + RoPE + scatter to head-major ----------------
__global__ void qkvpost_kernel(const float* __restrict__ Y, const float* __restrict__ pe,
                               const float* __restrict__ q_scale, const float* __restrict__ k_scale,
                               float* __restrict__ Q, float* __restrict__ K, float* __restrict__ V) {
    int gw = blockIdx.x * 8 + (threadIdx.x >> 5);   // warp id: 0 .. 2304*16-1
    int lane = threadIdx.x & 31;
    int l = gw >> 4;
    int h = gw & 15;
    int i = (l < L_TXT) ? 2 : (l < (L_TXT + L_IMG) ? 0 : 1);
    bool is_tmp = (l >= L_TXT + L_IMG);

    const float* row = Y + (size_t)l * 3072 + h * HD;
    float q0 = row[2 * lane],        q1 = row[2 * lane + 1];
    float k0 = row[1024 + 2 * lane], k1 = row[1024 + 2 * lane + 1];
    float v0 = row[2048 + 2 * lane], v1 = row[2048 + 2 * lane + 1];

    float qs = q0 * q0 + q1 * q1;
    float ks = k0 * k0 + k1 * k1;
    #pragma unroll
    for (int o = 16; o; o >>= 1) {
        qs += __shfl_xor_sync(0xffffffffu, qs, o);
        ks += __shfl_xor_sync(0xffffffffu, ks, o);
    }
    float qinv = rsqrtf(qs * (1.f / HD) + EPS);
    float kinv = rsqrtf(ks * (1.f / HD) + EPS);

    float qn0 = q0 * qinv * q_scale[i * HD + 2 * lane];
    float qn1 = q1 * qinv * q_scale[i * HD + 2 * lane + 1];
    float kn0 = k0 * kinv * k_scale[i * HD + 2 * lane];
    float kn1 = k1 * kinv * k_scale[i * HD + 2 * lane + 1];

    const float* p = pe + ((size_t)l * 32 + lane) * 4;
    float p00 = p[0], p01 = p[1], p10 = p[2], p11 = p[3];

    size_t base = ((size_t)h * L_ALL + l) * HD + 2 * lane;
    Q[base]     = p00 * qn0 + p01 * qn1;
    Q[base + 1] = p10 * qn0 + p11 * qn1;
    K[base]     = p00 * kn0 + p01 * kn1;
    K[base + 1] = p10 * kn0 + p11 * kn1;
    if (is_tmp) { V[base] = qn0; V[base + 1] = qn1; }
    else        { V[base] = v0;  V[base + 1] = v1;  }
}

// ---------------- flash attention on tensor cores (tf32 mma) ----------------
#define ATQ 64
#define ATK 64
#define ALD 68

__global__ void __launch_bounds__(128) attn_tc_kernel(
        const float* __restrict__ Q, const float* __restrict__ K,
        const float* __restrict__ V, float* __restrict__ Aout) {
    extern __shared__ uint32_t dyn[];
    uint32_t (*Ks)[ALD] = (uint32_t(*)[ALD])dyn;
    uint32_t (*Vs)[ALD] = (uint32_t(*)[ALD])(dyn + ATK * ALD);
    uint32_t (*Ps)[ALD] = (uint32_t(*)[ALD])(dyn + 2 * ATK * ALD);

    int h   = blockIdx.y;
    int q0  = blockIdx.x * ATQ;
    int tid = threadIdx.x;          // 128
    int warp = tid >> 5;
    int lane = tid & 31;
    int gid  = lane >> 2;
    int tig  = lane & 3;
    int w16  = warp * 16;

    const float* Qh = Q + (size_t)h * L_ALL * HD;
    const float* Kh = K + (size_t)h * L_ALL * HD;
    const float* Vh = V + (size_t)h * L_ALL * HD;

    #pragma unroll
    for (int i = 0; i < 8; i++) {
        int linear = tid + i * 128;
        int r = linear >> 4;
        int c4 = (linear & 15) * 4;
        float4 qv = *(const float4*)(Qh + (size_t)(q0 + r) * HD + c4);
        Ps[r][c4 + 0] = f2tf32(qv.x * ATTN_SCALE);
        Ps[r][c4 + 1] = f2tf32(qv.y * ATTN_SCALE);
        Ps[r][c4 + 2] = f2tf32(qv.z * ATTN_SCALE);
        Ps[r][c4 + 3] = f2tf32(qv.w * ATTN_SCALE);
    }
    __syncthreads();

    uint32_t qf[8][4];
    #pragma unroll
    for (int ks = 0; ks < 8; ks++) {
        qf[ks][0] = Ps[w16 + gid][ks * 8 + tig];
        qf[ks][1] = Ps[w16 + gid + 8][ks * 8 + tig];
        qf[ks][2] = Ps[w16 + gid][ks * 8 + tig + 4];
        qf[ks][3] = Ps[w16 + gid + 8][ks * 8 + tig + 4];
    }

    float oacc[8][4];
    #pragma unroll
    for (int nt = 0; nt < 8; nt++)
        #pragma unroll
        for (int c = 0; c < 4; c++) oacc[nt][c] = 0.f;
    float m0 = -INFINITY, m1 = -INFINITY, l0 = 0.f, l1 = 0.f;

    for (int kb = 0; kb < L_ALL; kb += ATK) {
        __syncthreads();
        #pragma unroll
        for (int i = 0; i < 8; i++) {
            int linear = tid + i * 128;
            int r = linear >> 4;
            int c4 = (linear & 15) * 4;
            float4 kv = *(const float4*)(Kh + (size_t)(kb + r) * HD + c4);
            float4 vv = *(const float4*)(Vh + (size_t)(kb + r) * HD + c4);
            Ks[r][c4 + 0] = f2tf32(kv.x); Ks[r][c4 + 1] = f2tf32(kv.y);
            Ks[r][c4 + 2] = f2tf32(kv.z); Ks[r][c4 + 3] = f2tf32(kv.w);
            Vs[r][c4 + 0] = f2tf32(vv.x); Vs[r][c4 + 1] = f2tf32(vv.y);
            Vs[r][c4 + 2] = f2tf32(vv.z); Vs[r][c4 + 3] = f2tf32(vv.w);
        }
        __syncthreads();

        float sacc[8][4];
        #pragma unroll
        for (int nt = 0; nt < 8; nt++)
            #pragma unroll
            for (int c = 0; c < 4; c++) sacc[nt][c] = 0.f;
        #pragma unroll
        for (int ks = 0; ks < 8; ks++) {
            #pragma unroll
            for (int nt = 0; nt < 8; nt++) {
                uint32_t b0 = Ks[nt * 8 + gid][ks * 8 + tig];
                uint32_t b1 = Ks[nt * 8 + gid][ks * 8 + tig + 4];
                mma_tf32(sacc[nt][0], sacc[nt][1], sacc[nt][2], sacc[nt][3],
                         qf[ks][0], qf[ks][1], qf[ks][2], qf[ks][3], b0, b1);
            }
        }

        float t0 = -INFINITY, t1 = -INFINITY;
        #pragma unroll
        for (int nt = 0; nt < 8; nt++) {
            t0 = fmaxf(t0, fmaxf(sacc[nt][0], sacc[nt][1]));
            t1 = fmaxf(t1, fmaxf(sacc[nt][2], sacc[nt][3]));
        }
        t0 = fmaxf(t0, __shfl_xor_sync(0xffffffffu, t0, 1));
        t0 = fmaxf(t0, __shfl_xor_sync(0xffffffffu, t0, 2));
        t1 = fmaxf(t1, __shfl_xor_sync(0xffffffffu, t1, 1));
        t1 = fmaxf(t1, __shfl_xor_sync(0xffffffffu, t1, 2));
        float mn0 = fmaxf(m0, t0), mn1 = fmaxf(m1, t1);
        float al0 = __expf(m0 - mn0), al1 = __expf(m1 - mn1);
        m0 = mn0; m1 = mn1;

        float ts0 = 0.f, ts1 = 0.f;
        #pragma unroll
        for (int nt = 0; nt < 8; nt++) {
            int c0 = nt * 8 + tig * 2;
            uint32_t p00 = f2tf32(__expf(sacc[nt][0] - mn0));
            uint32_t p01 = f2tf32(__expf(sacc[nt][1] - mn0));
            uint32_t p10 = f2tf32(__expf(sacc[nt][2] - mn1));
            uint32_t p11 = f2tf32(__expf(sacc[nt][3] - mn1));
            Ps[w16 + gid][c0]         = p00;
            Ps[w16 + gid][c0 + 1]     = p01;
            Ps[w16 + gid + 8][c0]     = p10;
            Ps[w16 + gid + 8][c0 + 1] = p11;
            ts0 += __uint_as_float(p00) + __uint_as_float(p01);
            ts1 += __uint_as_float(p10) + __uint_as_float(p11);
        }
        ts0 += __shfl_xor_sync(0xffffffffu, ts0, 1);
        ts0 += __shfl_xor_sync(0xffffffffu, ts0, 2);
        ts1 += __shfl_xor_sync(0xffffffffu, ts1, 1);
        ts1 += __shfl_xor_sync(0xffffffffu, ts1, 2);
        l0 = l0 * al0 + ts0;
        l1 = l1 * al1 + ts1;

        #pragma unroll
        for (int nt = 0; nt < 8; nt++) {
            oacc[nt][0] *= al0; oacc[nt][1] *= al0;
            oacc[nt][2] *= al1; oacc[nt][3] *= al1;
        }
        __syncwarp();

        #pragma unroll
        for (int ks = 0; ks < 8; ks++) {
            uint32_t a0 = Ps[w16 + gid][ks * 8 + tig];
            uint32_t a1 = Ps[w16 + gid + 8][ks * 8 + tig];
            uint32_t a2 = Ps[w16 + gid][ks * 8 + tig + 4];
            uint32_t a3 = Ps[w16 + gid + 8][ks * 8 + tig + 4];
            #pragma unroll
            for (int nt = 0; nt < 8; nt++) {
                uint32_t b0 = Vs[ks * 8 + tig][nt * 8 + gid];
                uint32_t b1 = Vs[ks * 8 + tig + 4][nt * 8 + gid];
                mma_tf32(oacc[nt][0], oacc[nt][1], oacc[nt][2], oacc[nt][3],
                         a0, a1, a2, a3, b0, b1);
            }
        }
        __syncwarp();
    }

    float i0 = 1.f / l0, i1 = 1.f / l1;
    int r0 = q0 + w16 + gid;
    int r1 = r0 + 8;
    #pragma unroll
    for (int nt = 0; nt < 8; nt++) {
        int c0 = h * HD + nt * 8 + tig * 2;
        Aout[(size_t)r0 * D_MODEL + c0]     = oacc[nt][0] * i0;
        Aout[(size_t)r0 * D_MODEL + c0 + 1] = oacc[nt][1] * i0;
        Aout[(size_t)r1 * D_MODEL + c0]     = oacc[nt][2] * i1;
        Aout[(size_t)r1 * D_MODEL + c0 + 1] = oacc[nt][3] * i1;
    }
}

#define ATTN_SMEM (3 * ATK * ALD * 4)

extern "C" void kernel_launch(void* const* d_in, const int* in_sizes, int n_in,
                              void* d_out, int out_size) {
    const float* img      = (const float*)d_in[0];
    const float* temporal = (const float*)d_in[1];
    const float* txt      = (const float*)d_in[2];
    const float* vec      = (const float*)d_in[3];
    const float* pe       = (const float*)d_in[4];
    const float* mod_w    = (const float*)d_in[5];
    const float* mod_b    = (const float*)d_in[6];
    const float* qkv_w    = (const float*)d_in[7];
    const float* q_scale  = (const float*)d_in[8];
    const float* k_scale  = (const float*)d_in[9];
    const float* proj_w   = (const float*)d_in[10];
    const float* proj_b   = (const float*)d_in[11];
    const float* mlp_w1   = (const float*)d_in[12];
    const float* mlp_b1   = (const float*)d_in[13];
    const float* mlp_w2   = (const float*)d_in[14];
    const float* mlp_b2   = (const float*)d_in[15];
    float* out = (float*)d_out;

    static float *sv = 0, *mod = 0, *res = 0, *xm = 0, *qkv = 0, *Qb = 0, *Kb = 0, *Vb = 0,
                 *attn = 0, *x1 = 0, *ym = 0, *hbuf = 0;
    if (!sv) {
        cudaGetSymbolAddress((void**)&sv,   g_sv);
        cudaGetSymbolAddress((void**)&mod,  g_mod);
        cudaGetSymbolAddress((void**)&res,  g_res);
        cudaGetSymbolAddress((void**)&xm,   g_xm);
        cudaGetSymbolAddress((void**)&qkv,  g_qkv);
        cudaGetSymbolAddress((void**)&Qb,   g_Q);
        cudaGetSymbolAddress((void**)&Kb,   g_K);
        cudaGetSymbolAddress((void**)&Vb,   g_V);
        cudaGetSymbolAddress((void**)&attn, g_attn);
        cudaGetSymbolAddress((void**)&x1,   g_x1);
        cudaGetSymbolAddress((void**)&ym,   g_ym);
        cudaGetSymbolAddress((void**)&hbuf, g_h);
        cudaFuncSetAttribute(attn_tc_kernel,
                             cudaFuncAttributeMaxDynamicSharedMemorySize, ATTN_SMEM);
    }

    const int off_txt = 0;
    const int off_img = L_TXT;
    const int off_tmp = L_TXT + L_IMG;

    // 1. independent prep
    silu_kernel<<<1, 1024>>>(vec, sv);
    copy3_kernel<<<(L_ALL * D_MODEL / 4) / 256, 256>>>(txt, img, temporal, res);
    mod_kernel<<<(3 * 6144) / 256, 256>>>(sv, mod_w, mod_b, mod);

    // 2. LN1 + modulate
    lnmod_kernel<<<L_TXT, 256>>>(txt,      xm + (size_t)off_txt * D_MODEL, mod + 2 * 6144, mod + 2 * 6144 + 1024);
    lnmod_kernel<<<L_IMG, 256>>>(img,      xm + (size_t)off_img * D_MODEL, mod + 0,        mod + 1024);
    lnmod_kernel<<<L_TMP, 256>>>(temporal, xm + (size_t)off_tmp * D_MODEL, mod + 1 * 6144, mod + 1 * 6144 + 1024);

    // 3. QKV (batched z=3: txt->w2, img->w0, tmp->w1)
    {
        BArgs ba = {};
        int ao[3] = {off_txt, off_img, off_tmp};
        for (int z = 0; z < 3; z++) { ba.aoff[z] = ao[z]; ba.coff[z] = ao[z]; }
        ba.m[0] = 256; ba.m[1] = 1024; ba.m[2] = 1024;
        ba.woff[0] = 2LL * 1024 * 3072; ba.woff[1] = 0; ba.woff[2] = 1LL * 1024 * 3072;
        gemm_tc_kernel<<<dim3(3072 / TBN, 16, 3), 256>>>(xm, qkv_w, qkv, 3072, 1024,
                                                         proj_b, mod, res, 0, ba);
    }

    // 4. RMS + scale + RoPE + scatter
    qkvpost_kernel<<<(L_ALL * NH) / 8, 256>>>(qkv, pe, q_scale, k_scale, Qb, Kb, Vb);

    // 5. attention
    attn_tc_kernel<<<dim3(L_ALL / ATQ, NH), 128, ATTN_SMEM>>>(Qb, Kb, Vb, attn);

    // 6. proj + gate + residual (batched z=3)
    {
        BArgs ba = {};
        int ao[3] = {off_txt, off_img, off_tmp};
        int wi[3] = {2, 0, 1};
        for (int z = 0; z < 3; z++) {
            ba.aoff[z] = ao[z]; ba.coff[z] = ao[z]; ba.roff[z] = ao[z];
            ba.woff[z] = (long long)wi[z] * 1024 * 1024;
            ba.boff[z] = wi[z] * 1024;
            ba.goff[z] = wi[z] * 6144 + 2048;
        }
        ba.m[0] = 256; ba.m[1] = 1024; ba.m[2] = 1024;
        gemm_tc_kernel<<<dim3(1024 / TBN, 16, 3), 256>>>(attn, proj_w, x1, 1024, 1024,
                                                         proj_b, mod, res, 2, ba);
    }

    // 7. img + txt MLP (batched z=2); temporal must wait for final img
    lnmod_kernel<<<L_IMG, 256>>>(x1 + (size_t)off_img * D_MODEL, ym,
                                 mod + 0 * 6144 + 3072, mod + 0 * 6144 + 4096);
    lnmod_kernel<<<L_TXT, 256>>>(x1 + (size_t)off_txt * D_MODEL, ym + (size_t)1024 * D_MODEL,
                                 mod + 2 * 6144 + 3072, mod + 2 * 6144 + 4096);
    {
        BArgs ba = {};
        ba.aoff[0] = 0;    ba.coff[0] = 0;    ba.m[0] = 1024;
        ba.woff[0] = 0;    ba.boff[0] = 0;
        ba.aoff[1] = 1024; ba.coff[1] = 1024; ba.m[1] = 256;
        ba.woff[1] = 2LL * 1024 * 4096; ba.boff[1] = 2 * 4096;
        gemm_tc_kernel<<<dim3(4096 / TBN, 16, 2), 256>>>(ym, mlp_w1, hbuf, 4096, 1024,
                                                         mlp_b1, mod, res, 1, ba);
    }
    {
        BArgs ba = {};
        // z0: img -> out rows [0,1024), res = x1 img rows
        ba.aoff[0] = 0;    ba.coff[0] = 0;    ba.roff[0] = off_img; ba.m[0] = 1024;
        ba.woff[0] = 0;    ba.boff[0] = 0;    ba.goff[0] = 0 * 6144 + 5120;
        // z1: txt -> out rows [2048,2304), res = x1 txt rows
        ba.aoff[1] = 1024; ba.coff[1] = 2048; ba.roff[1] = off_txt; ba.m[1] = 256;
        ba.woff[1] = 2LL * 4096 * 1024; ba.boff[1] = 2 * 1024; ba.goff[1] = 2 * 6144 + 5120;
        gemm_tc_kernel<<<dim3(1024 / TBN, 16, 2), 256>>>(hbuf, mlp_w2, out, 1024, 4096,
                                                         mlp_b2, mod, x1, 2, ba);
    }

    // 8. temporal MLP: LN of FINAL img (reference quirk), residual = x1 tmp rows
    lnmod_kernel<<<L_TMP, 256>>>(out, ym, mod + 1 * 6144 + 3072, mod + 1 * 6144 + 4096);
    {
        BArgs ba = {};
        ba.aoff[0] = 0; ba.coff[0] = 0; ba.m[0] = 1024;
        ba.woff[0] = 1LL * 1024 * 4096; ba.boff[0] = 4096;
        gemm_tc_kernel<<<dim3(4096 / TBN, 16, 1), 256>>>(ym, mlp_w1, hbuf, 4096, 1024,
                                                         mlp_b1, mod, res, 1, ba);
    }
    {
        BArgs ba = {};
        ba.aoff[0] = 0; ba.coff[0] = 1024; ba.roff[0] = off_tmp; ba.m[0] = 1024;
        ba.woff[0] = 1LL * 4096 * 1024; ba.boff[0] = 1024; ba.goff[0] = 1 * 6144 + 5120;
        gemm_tc_kernel<<<dim3(1024 / TBN, 16, 1), 256>>>(hbuf, mlp_w2, out, 1024, 4096,
                                                         mlp_b2, mod, x1, 2, ba);
    }
}

// round 8
// speedup vs baseline: 5.7445x; 1.1463x over previous
#include <cuda_runtime.h>
#include <cuda_bf16.h>
#include <math.h>
#include <stdint.h>

// ---------------- problem constants ----------------
#define L_TXT 256
#define L_IMG 1024
#define L_TMP 1024
#define L_ALL 2304          // txt + img + tmp
#define D_MODEL 1024
#define NH 16
#define HD 64
#define D_MLP 4096
#define EPS 1e-6f
#define ATTN_SCALE 0.125f   // 1/sqrt(64)

// ---------------- scratch (static device memory; no allocation) ----------------
__device__ float g_sv[D_MODEL];
__device__ float g_mod[3 * 6144];
__device__ float g_res[L_ALL * D_MODEL];       // concat copy of original inputs [txt|img|tmp]
__device__ float g_xm[L_ALL * D_MODEL];        // LN1-modulated, concat order [txt|img|tmp]
__device__ float g_qkv[L_ALL * 3 * D_MODEL];   // QKV gemm out, same row order
__device__ float g_Q[NH * L_ALL * HD];
__device__ float g_K[NH * L_ALL * HD];
__device__ float g_V[NH * L_ALL * HD];
__device__ float g_attn[L_ALL * D_MODEL];      // [l][h*64+d], concat order
__device__ float g_x1[L_ALL * D_MODEL];        // post-proj residual, concat order
__device__ float g_ym[1280 * D_MODEL];         // LN2-modulated (img rows 0..1023, txt rows 1024..1279)
__device__ float g_h[1280 * D_MLP];            // MLP hidden

// ---------------- helpers ----------------
__device__ __forceinline__ float gelu_tanh(float x) {
    const float c = 0.7978845608028654f; // sqrt(2/pi)
    float x3 = x * x * x;
    return 0.5f * x * (1.f + tanhf(c * (x + 0.044715f * x3)));
}

__device__ __forceinline__ uint32_t f2tf32(float f) {
    uint32_t u;
    asm("cvt.rna.tf32.f32 %0, %1;" : "=r"(u) : "f"(f));
    return u;
}

__device__ __forceinline__ void mma_tf32(float& d0, float& d1, float& d2, float& d3,
                                         uint32_t a0, uint32_t a1, uint32_t a2, uint32_t a3,
                                         uint32_t b0, uint32_t b1) {
    asm volatile(
        "mma.sync.aligned.m16n8k8.row.col.f32.tf32.tf32.f32 "
        "{%0,%1,%2,%3}, {%4,%5,%6,%7}, {%8,%9}, {%0,%1,%2,%3};"
        : "+f"(d0), "+f"(d1), "+f"(d2), "+f"(d3)
        : "r"(a0), "r"(a1), "r"(a2), "r"(a3), "r"(b0), "r"(b1));
}

// ---------------- silu(vec) ----------------
__global__ void silu_kernel(const float* __restrict__ v, float* __restrict__ sv) {
    int t = threadIdx.x;
    float x = v[t];
    sv[t] = x / (1.f + expf(-x));
}

// ---------------- concat copy of residual sources ----------------
__global__ void copy3_kernel(const float* __restrict__ txt, const float* __restrict__ img,
                             const float* __restrict__ tmp, float* __restrict__ dst) {
    int i = blockIdx.x * 256 + threadIdx.x;    // float4 index, total L_ALL*1024/4
    const int ntxt = L_TXT * D_MODEL / 4;
    const int nimg = (L_TXT + L_IMG) * D_MODEL / 4;
    float4 v;
    if (i < ntxt)       v = ((const float4*)txt)[i];
    else if (i < nimg)  v = ((const float4*)img)[i - ntxt];
    else                v = ((const float4*)tmp)[i - nimg];
    ((float4*)dst)[i] = v;
}

// ---------------- mod = sv @ mod_w + mod_b  (3 x 6144 outputs) ----------------
__global__ void mod_kernel(const float* __restrict__ sv, const float* __restrict__ mod_w,
                           const float* __restrict__ mod_b, float* __restrict__ mod) {
    __shared__ float s_sv[D_MODEL];
    for (int i = threadIdx.x; i < D_MODEL; i += 256) s_sv[i] = sv[i];
    __syncthreads();
    int o = blockIdx.x * 256 + threadIdx.x;       // 0 .. 3*6144-1
    int i = o / 6144;
    int j = o - i * 6144;
    const float* w = mod_w + (size_t)i * D_MODEL * 6144 + j;
    float acc = 0.f;
    #pragma unroll 8
    for (int d = 0; d < D_MODEL; ++d) acc = fmaf(s_sv[d], w[(size_t)d * 6144], acc);
    mod[o] = acc + mod_b[o];
}

// ---------------- LN + modulate: out = (1+sc)*ln(x) + sh ----------------
__global__ void lnmod_kernel(const float* __restrict__ x, float* __restrict__ out,
                             const float* __restrict__ sh, const float* __restrict__ sc) {
    int r = blockIdx.x;
    const float* xr = x + (size_t)r * D_MODEL;
    int t = threadIdx.x; // 256
    float v[4]; float sum = 0.f, sq = 0.f;
    #pragma unroll
    for (int i = 0; i < 4; i++) { float f = xr[t + i * 256]; v[i] = f; sum += f; sq += f * f; }
    #pragma unroll
    for (int o = 16; o; o >>= 1) {
        sum += __shfl_xor_sync(0xffffffffu, sum, o);
        sq  += __shfl_xor_sync(0xffffffffu, sq, o);
    }
    __shared__ float ssum[8], ssq[8];
    int w = t >> 5, lane = t & 31;
    if (lane == 0) { ssum[w] = sum; ssq[w] = sq; }
    __syncthreads();
    if (t == 0) {
        float S = 0.f, Q = 0.f;
        #pragma unroll
        for (int i = 0; i < 8; i++) { S += ssum[i]; Q += ssq[i]; }
        float mean = S * (1.f / D_MODEL);
        float var  = Q * (1.f / D_MODEL) - mean * mean;
        ssum[0] = mean; ssq[0] = rsqrtf(var + EPS);
    }
    __syncthreads();
    float mean = ssum[0], inv = ssq[0];
    float* orow = out + (size_t)r * D_MODEL;
    #pragma unroll
    for (int i = 0; i < 4; i++) {
        int d = t + i * 256;
        orow[d] = (1.f + sc[d]) * ((v[i] - mean) * inv) + sh[d];
    }
}

// ---------------- tf32 tensor-core GEMM, 64x128x32 tiles, fragment-packed, z-batched ----------------
// epi 0: C = acc;  epi 1: C = gelu(acc + bias);  epi 2: C = res + gate*(acc + bias)
// Staging buffers in DYNAMIC smem (50368 B > 48KB static cap).
#define TBM 64
#define TBN 128
#define TBK 32
// A fragment store: [oct(4)][mblk(4)][lane(32)][4 words] + pad
#define A_OCT 516           // 4*32*4 + 4
#define A_STAGE (4 * A_OCT)
// B fragment store: [oct(4)][nblk(16) stride 66][lane*2 + slot]
#define B_NB 66
#define B_OCT 1058          // 16*66 + 2
#define B_STAGE (4 * B_OCT)
#define GEMM_SMEM ((2 * A_STAGE + 2 * B_STAGE) * 4)   // 50368 bytes

struct BArgs {
    int aoff[3];      // A row offset per z
    int coff[3];      // C row offset per z
    int roff[3];      // res row offset per z
    int m[3];         // rows per z
    long long woff[3];// weight element offset per z
    int boff[3];      // bias element offset per z
    int goff[3];      // gate element offset per z
};

__global__ void __launch_bounds__(256) gemm_tc_kernel(
        const float* __restrict__ A, const float* __restrict__ W,
        float* __restrict__ C, int N, int K,
        const float* __restrict__ bias,
        const float* __restrict__ gate,
        const float* __restrict__ res,
        int epi, BArgs ba) {
    int z = blockIdx.z;
    int brow = blockIdx.y, bcol = blockIdx.x;
    if (brow * TBM >= ba.m[z]) return;

    extern __shared__ uint32_t gsm[];
    uint32_t (*As)[A_STAGE] = (uint32_t(*)[A_STAGE])gsm;
    uint32_t (*Bs)[B_STAGE] = (uint32_t(*)[B_STAGE])(gsm + 2 * A_STAGE);

    int tid  = threadIdx.x;
    int warp = tid >> 5;
    int lane = tid & 31;
    int gid  = lane >> 2;
    int tig  = lane & 3;
    int wm2  = (warp >> 2) * 2;     // mblk base (0 or 2)
    int wn8  = (warp & 3) * 4;      // nblk base

    const float* Ab = A + (size_t)ba.aoff[z] * K;
    const float* Bb = W + ba.woff[z];

    // global load mapping: A tile 64x32 = 512 float4 -> 2 per thread
    int al0 = tid, al1 = tid + 256;
    int a_row0 = al0 >> 3, a_kq0 = (al0 & 7) * 4;
    int a_row1 = al1 >> 3, a_kq1 = (al1 & 7) * 4;
    int abase0 = (a_kq0 >> 3) * A_OCT + (a_row0 >> 4) * 128 + (a_row0 & 7) * 16
               + ((a_row0 >> 3) & 1) * 2 + ((a_kq0 >> 2) & 1);
    int abase1 = (a_kq1 >> 3) * A_OCT + (a_row1 >> 4) * 128 + (a_row1 & 7) * 16
               + ((a_row1 >> 3) & 1) * 2 + ((a_kq1 >> 2) & 1);

    // B tile 32x128 = 2048 float2 -> 8 per thread; k rows b_row + r*4, r=0..7
    int b_row = tid >> 6;              // 0..3
    int b_col = (tid & 63) * 2;        // 0..126

    const float* Aptr0 = Ab + (size_t)(brow * TBM + a_row0) * K + a_kq0;
    const float* Aptr1 = Ab + (size_t)(brow * TBM + a_row1) * K + a_kq1;
    const float* Bptr  = Bb + (size_t)b_row * N + bcol * TBN + b_col;

    float acc[2][4][4];
    #pragma unroll
    for (int i = 0; i < 2; i++)
        #pragma unroll
        for (int j = 0; j < 4; j++)
            #pragma unroll
            for (int c = 0; c < 4; c++) acc[i][j][c] = 0.f;

    int iters = K / TBK;

    float4 av0 = *(const float4*)(Aptr0);
    float4 av1 = *(const float4*)(Aptr1);
    float2 bv[8];
    #pragma unroll
    for (int r = 0; r < 8; r++)
        bv[r] = *(const float2*)(Bptr + (size_t)(r * 4) * N);

    // store tile into fragment layout (raw f32 bits; HMMA truncates to tf32)
    #define STORE_TILE(BUF) do {                                                     \
        As[BUF][abase0 + 0]  = __float_as_uint(av0.x);                               \
        As[BUF][abase0 + 4]  = __float_as_uint(av0.y);                               \
        As[BUF][abase0 + 8]  = __float_as_uint(av0.z);                               \
        As[BUF][abase0 + 12] = __float_as_uint(av0.w);                               \
        As[BUF][abase1 + 0]  = __float_as_uint(av1.x);                               \
        As[BUF][abase1 + 4]  = __float_as_uint(av1.y);                               \
        As[BUF][abase1 + 8]  = __float_as_uint(av1.z);                               \
        As[BUF][abase1 + 12] = __float_as_uint(av1.w);                               \
        _Pragma("unroll")                                                            \
        for (int r = 0; r < 8; r++) {                                                \
            int k   = b_row + r * 4;                                                 \
            int oct = k >> 3;                                                        \
            int j   = k & 7;                                                         \
            int jm  = j & 3;                                                         \
            int sl  = j >> 2;                                                        \
            int n7  = b_col & 7;                                                     \
            int nbl = b_col >> 3;                                                    \
            uint32_t* bb = &Bs[BUF][oct * B_OCT + nbl * B_NB + sl];                  \
            bb[(n7 * 4 + jm) * 2]       = __float_as_uint(bv[r].x);                  \
            bb[((n7 + 1) * 4 + jm) * 2] = __float_as_uint(bv[r].y);                  \
        }                                                                            \
    } while (0)

    STORE_TILE(0);
    __syncthreads();

    for (int it = 0; it < iters; ++it) {
        int cur = it & 1;
        if (it + 1 < iters) {
            int k0 = (it + 1) * TBK;
            av0 = *(const float4*)(Aptr0 + k0);
            av1 = *(const float4*)(Aptr1 + k0);
            #pragma unroll
            for (int r = 0; r < 8; r++)
                bv[r] = *(const float2*)(Bptr + (size_t)(k0 + r * 4) * N);
        }

        #pragma unroll
        for (int oct = 0; oct < 4; oct++) {
            uint4 ua[2];
            #pragma unroll
            for (int mt = 0; mt < 2; mt++)
                ua[mt] = *(const uint4*)&As[cur][oct * A_OCT + (wm2 + mt) * 128 + lane * 4];
            uint2 ub[4];
            #pragma unroll
            for (int nt = 0; nt < 4; nt++)
                ub[nt] = *(const uint2*)&Bs[cur][oct * B_OCT + (wn8 + nt) * B_NB + lane * 2];
            #pragma unroll
            for (int mt = 0; mt < 2; mt++)
                #pragma unroll
                for (int nt = 0; nt < 4; nt++)
                    mma_tf32(acc[mt][nt][0], acc[mt][nt][1], acc[mt][nt][2], acc[mt][nt][3],
                             ua[mt].x, ua[mt].z, ua[mt].y, ua[mt].w,
                             ub[nt].x, ub[nt].y);
        }

        if (it + 1 < iters) {
            int nxt = cur ^ 1;
            STORE_TILE(nxt);
            __syncthreads();
        }
    }
    #undef STORE_TILE

    // epilogue
    int wm = (warp >> 2) * 32;
    int wn = (warp & 3) * 32;
    int crow = ba.coff[z];
    int rrow = ba.roff[z];
    int bo = ba.boff[z], go = ba.goff[z];
    #pragma unroll
    for (int mt = 0; mt < 2; mt++) {
        int lrow0 = brow * TBM + wm + mt * 16 + gid;
        int lrow1 = lrow0 + 8;
        #pragma unroll
        for (int nt = 0; nt < 4; nt++) {
            int col0 = bcol * TBN + wn + nt * 8 + tig * 2;
            int col1 = col0 + 1;
            float v0 = acc[mt][nt][0], v1 = acc[mt][nt][1];
            float v2 = acc[mt][nt][2], v3 = acc[mt][nt][3];
            if (epi == 1) {
                v0 = gelu_tanh(v0 + bias[bo + col0]); v1 = gelu_tanh(v1 + bias[bo + col1]);
                v2 = gelu_tanh(v2 + bias[bo + col0]); v3 = gelu_tanh(v3 + bias[bo + col1]);
            } else if (epi == 2) {
                v0 = res[(size_t)(rrow + lrow0) * N + col0] + gate[go + col0] * (v0 + bias[bo + col0]);
                v1 = res[(size_t)(rrow + lrow0) * N + col1] + gate[go + col1] * (v1 + bias[bo + col1]);
                v2 = res[(size_t)(rrow + lrow1) * N + col0] + gate[go + col0] * (v2 + bias[bo + col0]);
                v3 = res[(size_t)(rrow + lrow1) * N + col1] + gate[go + col1] * (v3 + bias[bo + col1]);
            }
            C[(size_t)(crow + lrow0) * N + col0] = v0;
            C[(size_t)(crow + lrow0) * N + col1] = v1;
            C[(size_t)(crow + lrow1) * N + col0] = v2;
            C[(size_t)(crow + lrow1) * N + col1] = v3;
        }
    }
}

// ---------------- QKV post: RMS + scale + RoPE + scatter to head-major ----------------
__global__ void qkvpost_kernel(const float* __restrict__ Y, const float* __restrict__ pe,
                               const float* __restrict__ q_scale, const float* __restrict__ k_scale,
                               float* __restrict__ Q, float* __restrict__ K, float* __restrict__ V) {
    int gw = blockIdx.x * 8 + (threadIdx.x >> 5);   // warp id: 0 .. 2304*16-1
    int lane = threadIdx.x & 31;
    int l = gw >> 4;
    int h = gw & 15;
    int i = (l < L_TXT) ? 2 : (l < (L_TXT + L_IMG) ? 0 : 1);
    bool is_tmp = (l >= L_TXT + L_IMG);

    const float* row = Y + (size_t)l * 3072 + h * HD;
    float q0 = row[2 * lane],        q1 = row[2 * lane + 1];
    float k0 = row[1024 + 2 * lane], k1 = row[1024 + 2 * lane + 1];
    float v0 = row[2048 + 2 * lane], v1 = row[2048 + 2 * lane + 1];

    float qs = q0 * q0 + q1 * q1;
    float ks = k0 * k0 + k1 * k1;
    #pragma unroll
    for (int o = 16; o; o >>= 1) {
        qs += __shfl_xor_sync(0xffffffffu, qs, o);
        ks += __shfl_xor_sync(0xffffffffu, ks, o);
    }
    float qinv = rsqrtf(qs * (1.f / HD) + EPS);
    float kinv = rsqrtf(ks * (1.f / HD) + EPS);

    float qn0 = q0 * qinv * q_scale[i * HD + 2 * lane];
    float qn1 = q1 * qinv * q_scale[i * HD + 2 * lane + 1];
    float kn0 = k0 * kinv * k_scale[i * HD + 2 * lane];
    float kn1 = k1 * kinv * k_scale[i * HD + 2 * lane + 1];

    const float* p = pe + ((size_t)l * 32 + lane) * 4;
    float p00 = p[0], p01 = p[1], p10 = p[2], p11 = p[3];

    size_t base = ((size_t)h * L_ALL + l) * HD + 2 * lane;
    Q[base]     = p00 * qn0 + p01 * qn1;
    Q[base + 1] = p10 * qn0 + p11 * qn1;
    K[base]     = p00 * kn0 + p01 * kn1;
    K[base + 1] = p10 * kn0 + p11 * kn1;
    if (is_tmp) { V[base] = qn0; V[base + 1] = qn1; }
    else        { V[base] = v0;  V[base + 1] = v1;  }
}

// ---------------- flash attention on tensor cores (tf32 mma) ----------------
#define ATQ 64
#define ATK 64
#define ALD 68

__global__ void __launch_bounds__(128) attn_tc_kernel(
        const float* __restrict__ Q, const float* __restrict__ K,
        const float* __restrict__ V, float* __restrict__ Aout) {
    extern __shared__ uint32_t dyn[];
    uint32_t (*Ks)[ALD] = (uint32_t(*)[ALD])dyn;
    uint32_t (*Vs)[ALD] = (uint32_t(*)[ALD])(dyn + ATK * ALD);
    uint32_t (*Ps)[ALD] = (uint32_t(*)[ALD])(dyn + 2 * ATK * ALD);

    int h   = blockIdx.y;
    int q0  = blockIdx.x * ATQ;
    int tid = threadIdx.x;          // 128
    int warp = tid >> 5;
    int lane = tid & 31;
    int gid  = lane >> 2;
    int tig  = lane & 3;
    int w16  = warp * 16;

    const float* Qh = Q + (size_t)h * L_ALL * HD;
    const float* Kh = K + (size_t)h * L_ALL * HD;
    const float* Vh = V + (size_t)h * L_ALL * HD;

    #pragma unroll
    for (int i = 0; i < 8; i++) {
        int linear = tid + i * 128;
        int r = linear >> 4;
        int c4 = (linear & 15) * 4;
        float4 qv = *(const float4*)(Qh + (size_t)(q0 + r) * HD + c4);
        Ps[r][c4 + 0] = f2tf32(qv.x * ATTN_SCALE);
        Ps[r][c4 + 1] = f2tf32(qv.y * ATTN_SCALE);
        Ps[r][c4 + 2] = f2tf32(qv.z * ATTN_SCALE);
        Ps[r][c4 + 3] = f2tf32(qv.w * ATTN_SCALE);
    }
    __syncthreads();

    uint32_t qf[8][4];
    #pragma unroll
    for (int ks = 0; ks < 8; ks++) {
        qf[ks][0] = Ps[w16 + gid][ks * 8 + tig];
        qf[ks][1] = Ps[w16 + gid + 8][ks * 8 + tig];
        qf[ks][2] = Ps[w16 + gid][ks * 8 + tig + 4];
        qf[ks][3] = Ps[w16 + gid + 8][ks * 8 + tig + 4];
    }

    float oacc[8][4];
    #pragma unroll
    for (int nt = 0; nt < 8; nt++)
        #pragma unroll
        for (int c = 0; c < 4; c++) oacc[nt][c] = 0.f;
    float m0 = -INFINITY, m1 = -INFINITY, l0 = 0.f, l1 = 0.f;

    for (int kb = 0; kb < L_ALL; kb += ATK) {
        __syncthreads();
        #pragma unroll
        for (int i = 0; i < 8; i++) {
            int linear = tid + i * 128;
            int r = linear >> 4;
            int c4 = (linear & 15) * 4;
            float4 kv = *(const float4*)(Kh + (size_t)(kb + r) * HD + c4);
            float4 vv = *(const float4*)(Vh + (size_t)(kb + r) * HD + c4);
            Ks[r][c4 + 0] = f2tf32(kv.x); Ks[r][c4 + 1] = f2tf32(kv.y);
            Ks[r][c4 + 2] = f2tf32(kv.z); Ks[r][c4 + 3] = f2tf32(kv.w);
            Vs[r][c4 + 0] = f2tf32(vv.x); Vs[r][c4 + 1] = f2tf32(vv.y);
            Vs[r][c4 + 2] = f2tf32(vv.z); Vs[r][c4 + 3] = f2tf32(vv.w);
        }
        __syncthreads();

        float sacc[8][4];
        #pragma unroll
        for (int nt = 0; nt < 8; nt++)
            #pragma unroll
            for (int c = 0; c < 4; c++) sacc[nt][c] = 0.f;
        #pragma unroll
        for (int ks = 0; ks < 8; ks++) {
            #pragma unroll
            for (int nt = 0; nt < 8; nt++) {
                uint32_t b0 = Ks[nt * 8 + gid][ks * 8 + tig];
                uint32_t b1 = Ks[nt * 8 + gid][ks * 8 + tig + 4];
                mma_tf32(sacc[nt][0], sacc[nt][1], sacc[nt][2], sacc[nt][3],
                         qf[ks][0], qf[ks][1], qf[ks][2], qf[ks][3], b0, b1);
            }
        }

        float t0 = -INFINITY, t1 = -INFINITY;
        #pragma unroll
        for (int nt = 0; nt < 8; nt++) {
            t0 = fmaxf(t0, fmaxf(sacc[nt][0], sacc[nt][1]));
            t1 = fmaxf(t1, fmaxf(sacc[nt][2], sacc[nt][3]));
        }
        t0 = fmaxf(t0, __shfl_xor_sync(0xffffffffu, t0, 1));
        t0 = fmaxf(t0, __shfl_xor_sync(0xffffffffu, t0, 2));
        t1 = fmaxf(t1, __shfl_xor_sync(0xffffffffu, t1, 1));
        t1 = fmaxf(t1, __shfl_xor_sync(0xffffffffu, t1, 2));
        float mn0 = fmaxf(m0, t0), mn1 = fmaxf(m1, t1);
        float al0 = __expf(m0 - mn0), al1 = __expf(m1 - mn1);
        m0 = mn0; m1 = mn1;

        float ts0 = 0.f, ts1 = 0.f;
        #pragma unroll
        for (int nt = 0; nt < 8; nt++) {
            int c0 = nt * 8 + tig * 2;
            uint32_t p00 = f2tf32(__expf(sacc[nt][0] - mn0));
            uint32_t p01 = f2tf32(__expf(sacc[nt][1] - mn0));
            uint32_t p10 = f2tf32(__expf(sacc[nt][2] - mn1));
            uint32_t p11 = f2tf32(__expf(sacc[nt][3] - mn1));
            Ps[w16 + gid][c0]         = p00;
            Ps[w16 + gid][c0 + 1]     = p01;
            Ps[w16 + gid + 8][c0]     = p10;
            Ps[w16 + gid + 8][c0 + 1] = p11;
            ts0 += __uint_as_float(p00) + __uint_as_float(p01);
            ts1 += __uint_as_float(p10) + __uint_as_float(p11);
        }
        ts0 += __shfl_xor_sync(0xffffffffu, ts0, 1);
        ts0 += __shfl_xor_sync(0xffffffffu, ts0, 2);
        ts1 += __shfl_xor_sync(0xffffffffu, ts1, 1);
        ts1 += __shfl_xor_sync(0xffffffffu, ts1, 2);
        l0 = l0 * al0 + ts0;
        l1 = l1 * al1 + ts1;

        #pragma unroll
        for (int nt = 0; nt < 8; nt++) {
            oacc[nt][0] *= al0; oacc[nt][1] *= al0;
            oacc[nt][2] *= al1; oacc[nt][3] *= al1;
        }
        __syncwarp();

        #pragma unroll
        for (int ks = 0; ks < 8; ks++) {
            uint32_t a0 = Ps[w16 + gid][ks * 8 + tig];
            uint32_t a1 = Ps[w16 + gid + 8][ks * 8 + tig];
            uint32_t a2 = Ps[w16 + gid][ks * 8 + tig + 4];
            uint32_t a3 = Ps[w16 + gid + 8][ks * 8 + tig + 4];
            #pragma unroll
            for (int nt = 0; nt < 8; nt++) {
                uint32_t b0 = Vs[ks * 8 + tig][nt * 8 + gid];
                uint32_t b1 = Vs[ks * 8 + tig + 4][nt * 8 + gid];
                mma_tf32(oacc[nt][0], oacc[nt][1], oacc[nt][2], oacc[nt][3],
                         a0, a1, a2, a3, b0, b1);
            }
        }
        __syncwarp();
    }

    float i0 = 1.f / l0, i1 = 1.f / l1;
    int r0 = q0 + w16 + gid;
    int r1 = r0 + 8;
    #pragma unroll
    for (int nt = 0; nt < 8; nt++) {
        int c0 = h * HD + nt * 8 + tig * 2;
        Aout[(size_t)r0 * D_MODEL + c0]     = oacc[nt][0] * i0;
        Aout[(size_t)r0 * D_MODEL + c0 + 1] = oacc[nt][1] * i0;
        Aout[(size_t)r1 * D_MODEL + c0]     = oacc[nt][2] * i1;
        Aout[(size_t)r1 * D_MODEL + c0 + 1] = oacc[nt][3] * i1;
    }
}

#define ATTN_SMEM (3 * ATK * ALD * 4)

extern "C" void kernel_launch(void* const* d_in, const int* in_sizes, int n_in,
                              void* d_out, int out_size) {
    const float* img      = (const float*)d_in[0];
    const float* temporal = (const float*)d_in[1];
    const float* txt      = (const float*)d_in[2];
    const float* vec      = (const float*)d_in[3];
    const float* pe       = (const float*)d_in[4];
    const float* mod_w    = (const float*)d_in[5];
    const float* mod_b    = (const float*)d_in[6];
    const float* qkv_w    = (const float*)d_in[7];
    const float* q_scale  = (const float*)d_in[8];
    const float* k_scale  = (const float*)d_in[9];
    const float* proj_w   = (const float*)d_in[10];
    const float* proj_b   = (const float*)d_in[11];
    const float* mlp_w1   = (const float*)d_in[12];
    const float* mlp_b1   = (const float*)d_in[13];
    const float* mlp_w2   = (const float*)d_in[14];
    const float* mlp_b2   = (const float*)d_in[15];
    float* out = (float*)d_out;

    static float *sv = 0, *mod = 0, *res = 0, *xm = 0, *qkv = 0, *Qb = 0, *Kb = 0, *Vb = 0,
                 *attn = 0, *x1 = 0, *ym = 0, *hbuf = 0;
    if (!sv) {
        cudaGetSymbolAddress((void**)&sv,   g_sv);
        cudaGetSymbolAddress((void**)&mod,  g_mod);
        cudaGetSymbolAddress((void**)&res,  g_res);
        cudaGetSymbolAddress((void**)&xm,   g_xm);
        cudaGetSymbolAddress((void**)&qkv,  g_qkv);
        cudaGetSymbolAddress((void**)&Qb,   g_Q);
        cudaGetSymbolAddress((void**)&Kb,   g_K);
        cudaGetSymbolAddress((void**)&Vb,   g_V);
        cudaGetSymbolAddress((void**)&attn, g_attn);
        cudaGetSymbolAddress((void**)&x1,   g_x1);
        cudaGetSymbolAddress((void**)&ym,   g_ym);
        cudaGetSymbolAddress((void**)&hbuf, g_h);
        cudaFuncSetAttribute(attn_tc_kernel,
                             cudaFuncAttributeMaxDynamicSharedMemorySize, ATTN_SMEM);
        cudaFuncSetAttribute(gemm_tc_kernel,
                             cudaFuncAttributeMaxDynamicSharedMemorySize, GEMM_SMEM);
    }

    const int off_txt = 0;
    const int off_img = L_TXT;
    const int off_tmp = L_TXT + L_IMG;

    // 1. independent prep
    silu_kernel<<<1, 1024>>>(vec, sv);
    copy3_kernel<<<(L_ALL * D_MODEL / 4) / 256, 256>>>(txt, img, temporal, res);
    mod_kernel<<<(3 * 6144) / 256, 256>>>(sv, mod_w, mod_b, mod);

    // 2. LN1 + modulate
    lnmod_kernel<<<L_TXT, 256>>>(txt,      xm + (size_t)off_txt * D_MODEL, mod + 2 * 6144, mod + 2 * 6144 + 1024);
    lnmod_kernel<<<L_IMG, 256>>>(img,      xm + (size_t)off_img * D_MODEL, mod + 0,        mod + 1024);
    lnmod_kernel<<<L_TMP, 256>>>(temporal, xm + (size_t)off_tmp * D_MODEL, mod + 1 * 6144, mod + 1 * 6144 + 1024);

    // 3. QKV (batched z=3: txt->w2, img->w0, tmp->w1)
    {
        BArgs ba = {};
        int ao[3] = {off_txt, off_img, off_tmp};
        for (int z = 0; z < 3; z++) { ba.aoff[z] = ao[z]; ba.coff[z] = ao[z]; }
        ba.m[0] = 256; ba.m[1] = 1024; ba.m[2] = 1024;
        ba.woff[0] = 2LL * 1024 * 3072; ba.woff[1] = 0; ba.woff[2] = 1LL * 1024 * 3072;
        gemm_tc_kernel<<<dim3(3072 / TBN, 16, 3), 256, GEMM_SMEM>>>(xm, qkv_w, qkv, 3072, 1024,
                                                                    proj_b, mod, res, 0, ba);
    }

    // 4. RMS + scale + RoPE + scatter
    qkvpost_kernel<<<(L_ALL * NH) / 8, 256>>>(qkv, pe, q_scale, k_scale, Qb, Kb, Vb);

    // 5. attention
    attn_tc_kernel<<<dim3(L_ALL / ATQ, NH), 128, ATTN_SMEM>>>(Qb, Kb, Vb, attn);

    // 6. proj + gate + residual (batched z=3)
    {
        BArgs ba = {};
        int ao[3] = {off_txt, off_img, off_tmp};
        int wi[3] = {2, 0, 1};
        for (int z = 0; z < 3; z++) {
            ba.aoff[z] = ao[z]; ba.coff[z] = ao[z]; ba.roff[z] = ao[z];
            ba.woff[z] = (long long)wi[z] * 1024 * 1024;
            ba.boff[z] = wi[z] * 1024;
            ba.goff[z] = wi[z] * 6144 + 2048;
        }
        ba.m[0] = 256; ba.m[1] = 1024; ba.m[2] = 1024;
        gemm_tc_kernel<<<dim3(1024 / TBN, 16, 3), 256, GEMM_SMEM>>>(attn, proj_w, x1, 1024, 1024,
                                                                    proj_b, mod, res, 2, ba);
    }

    // 7. img + txt MLP (batched z=2); temporal must wait for final img
    lnmod_kernel<<<L_IMG, 256>>>(x1 + (size_t)off_img * D_MODEL, ym,
                                 mod + 0 * 6144 + 3072, mod + 0 * 6144 + 4096);
    lnmod_kernel<<<L_TXT, 256>>>(x1 + (size_t)off_txt * D_MODEL, ym + (size_t)1024 * D_MODEL,
                                 mod + 2 * 6144 + 3072, mod + 2 * 6144 + 4096);
    {
        BArgs ba = {};
        ba.aoff[0] = 0;    ba.coff[0] = 0;    ba.m[0] = 1024;
        ba.woff[0] = 0;    ba.boff[0] = 0;
        ba.aoff[1] = 1024; ba.coff[1] = 1024; ba.m[1] = 256;
        ba.woff[1] = 2LL * 1024 * 4096; ba.boff[1] = 2 * 4096;
        gemm_tc_kernel<<<dim3(4096 / TBN, 16, 2), 256, GEMM_SMEM>>>(ym, mlp_w1, hbuf, 4096, 1024,
                                                                    mlp_b1, mod, res, 1, ba);
    }
    {
        BArgs ba = {};
        // z0: img -> out rows [0,1024), res = x1 img rows
        ba.aoff[0] = 0;    ba.coff[0] = 0;    ba.roff[0] = off_img; ba.m[0] = 1024;
        ba.woff[0] = 0;    ba.boff[0] = 0;    ba.goff[0] = 0 * 6144 + 5120;
        // z1: txt -> out rows [2048,2304), res = x1 txt rows
        ba.aoff[1] = 1024; ba.coff[1] = 2048; ba.roff[1] = off_txt; ba.m[1] = 256;
        ba.woff[1] = 2LL * 4096 * 1024; ba.boff[1] = 2 * 1024; ba.goff[1] = 2 * 6144 + 5120;
        gemm_tc_kernel<<<dim3(1024 / TBN, 16, 2), 256, GEMM_SMEM>>>(hbuf, mlp_w2, out, 1024, 4096,
                                                                    mlp_b2, mod, x1, 2, ba);
    }

    // 8. temporal MLP: LN of FINAL img (reference quirk), residual = x1 tmp rows
    lnmod_kernel<<<L_TMP, 256>>>(out, ym, mod + 1 * 6144 + 3072, mod + 1 * 6144 + 4096);
    {
        BArgs ba = {};
        ba.aoff[0] = 0; ba.coff[0] = 0; ba.m[0] = 1024;
        ba.woff[0] = 1LL * 1024 * 4096; ba.boff[0] = 4096;
        gemm_tc_kernel<<<dim3(4096 / TBN, 16, 1), 256, GEMM_SMEM>>>(ym, mlp_w1, hbuf, 4096, 1024,
                                                                    mlp_b1, mod, res, 1, ba);
    }
    {
        BArgs ba = {};
        ba.aoff[0] = 0; ba.coff[0] = 1024; ba.roff[0] = off_tmp; ba.m[0] = 1024;
        ba.woff[0] = 1LL * 4096 * 1024; ba.boff[0] = 1024; ba.goff[0] = 1 * 6144 + 5120;
        gemm_tc_kernel<<<dim3(1024 / TBN, 16, 1), 256, GEMM_SMEM>>>(hbuf, mlp_w2, out, 1024, 4096,
                                                                    mlp_b2, mod, x1, 2, ba);
    }
}